// round 2
// baseline (speedup 1.0000x reference)
#include <cuda_runtime.h>
#include <math.h>
#include <stdint.h>

#define Bx   8
#define Lx   4096
#define Dx   384
#define DIx  768
#define Sx   16
#define DTRx 24
#define Rx   (Bx*Lx)        /* 32768 rows */
#define NCH  32
#define CLEN (Lx/NCH)       /* 128 */

/* ------------- device scratch (static, no allocations) ------------- */
__device__ __align__(128) float g_xn [(size_t)Rx*Dx];
__device__ __align__(128) float g_xz [(size_t)Rx*2*DIx];
__device__ __align__(128) float g_xc [(size_t)Rx*DIx];
__device__ __align__(128) float g_dtr[(size_t)Rx*DTRx];
__device__ __align__(128) float g_Bmat[(size_t)Rx*Sx];
__device__ __align__(128) float g_Cmat[(size_t)Rx*Sx];
__device__ __align__(128) float g_dt [(size_t)Rx*DIx];
__device__ __align__(128) float g_yssm[(size_t)Rx*DIx];
__device__ __align__(128) float g_A  [DIx*Sx];
__device__ __align__(128) float g_hfin[(size_t)Bx*NCH*DIx*Sx];
__device__ __align__(128) float g_Hini[(size_t)Bx*NCH*DIx*Sx];
__device__ __align__(128) float g_dtsum[Bx*NCH*DIx];
__device__ __align__(128) float g_yvpart[Bx*NCH*DIx];
__device__ __align__(128) float g_xpart[Bx*16*Dx];
__device__ __align__(128) float g_pooled[Bx*Dx];
__device__ __align__(128) float g_hfc[Bx*256];

__device__ __forceinline__ float softplusf(float v) {
    return v > 20.f ? v : log1pf(__expf(v));
}
__device__ __forceinline__ float siluf(float v) {
    return v / (1.f + __expf(-v));
}

/* ------------- 1. RMSNorm ------------- */
__global__ __launch_bounds__(128) void rmsnorm_kernel(const float* __restrict__ x,
                                                      const float* __restrict__ w) {
    int row = blockIdx.x, tid = threadIdx.x;
    const float* xr = x + (size_t)row*Dx;
    float v0 = xr[tid], v1 = xr[tid+128], v2 = xr[tid+256];
    float ss = v0*v0 + v1*v1 + v2*v2;
    #pragma unroll
    for (int o = 16; o; o >>= 1) ss += __shfl_xor_sync(0xffffffffu, ss, o);
    __shared__ float sm[4];
    if ((tid & 31) == 0) sm[tid >> 5] = ss;
    __syncthreads();
    float tot = sm[0] + sm[1] + sm[2] + sm[3];
    float sc  = rsqrtf(tot * (1.f/Dx) + 1e-5f);
    float* o = g_xn + (size_t)row*Dx;
    o[tid]     = v0*sc*w[tid];
    o[tid+128] = v1*sc*w[tid+128];
    o[tid+256] = v2*sc*w[tid+256];
}

/* ------------- 2. GEMM1 (tensor core, split-tf32): g_xn[32768,384] @ W_in[384,1536] ------------- */
__device__ __forceinline__ uint32_t f2tf(float x) {
    uint32_t y;
    asm("cvt.rna.tf32.f32 %0, %1;" : "=r"(y) : "f"(x));
    return y;
}
__device__ __forceinline__ void mma_tf32(float* c, const uint32_t* a, const uint32_t* b) {
    asm volatile("mma.sync.aligned.m16n8k8.row.col.f32.tf32.tf32.f32 "
        "{%0,%1,%2,%3}, {%4,%5,%6,%7}, {%8,%9}, {%0,%1,%2,%3};\n"
        : "+f"(c[0]), "+f"(c[1]), "+f"(c[2]), "+f"(c[3])
        : "r"(a[0]), "r"(a[1]), "r"(a[2]), "r"(a[3]), "r"(b[0]), "r"(b[1]));
}

__global__ __launch_bounds__(256) void gemm_in_tc_kernel(const float* __restrict__ Wb) {
    const int N = 2*DIx;   /* 1536 */
    const int K = Dx;      /* 384  */
    __shared__ float As[128*20];   /* [m][k], stride 20 */
    __shared__ float Bs[16*136];   /* [k][n], stride 136 */
    int tid = threadIdx.x;
    int lane = tid & 31;
    int warp = tid >> 5;
    int warpM = warp >> 1;         /* 0..3 -> 32 rows */
    int warpN = warp & 1;          /* 0..1 -> 64 cols */
    int bn = blockIdx.x, bm = blockIdx.y;

    const float* Ag = g_xn + (size_t)(bm*128 + (tid>>1))*K + (tid&1)*8;
    const float* Bg = Wb + (size_t)(tid>>4)*N + bn*128 + (tid&15)*8;

    float4 pa0 = *(const float4*)(Ag);
    float4 pa1 = *(const float4*)(Ag + 4);
    float4 pb0 = *(const float4*)(Bg);
    float4 pb1 = *(const float4*)(Bg + 4);

    float acc[2][8][4];
    #pragma unroll
    for (int i = 0; i < 2; i++)
        #pragma unroll
        for (int j = 0; j < 8; j++)
            #pragma unroll
            for (int q = 0; q < 4; q++) acc[i][j][q] = 0.f;

    int g = lane >> 2, t = lane & 3;

    for (int kt = 0; kt < 24; kt++) {
        /* STS current tile */
        {
            int am = tid >> 1, ak = (tid & 1)*8;
            *(float4*)&As[am*20 + ak]     = pa0;
            *(float4*)&As[am*20 + ak + 4] = pa1;
            int bk = tid >> 4, bc = (tid & 15)*8;
            *(float4*)&Bs[bk*136 + bc]     = pb0;
            *(float4*)&Bs[bk*136 + bc + 4] = pb1;
        }
        __syncthreads();
        /* prefetch next tile */
        if (kt < 23) {
            pa0 = *(const float4*)(Ag + (kt+1)*16);
            pa1 = *(const float4*)(Ag + (kt+1)*16 + 4);
            pb0 = *(const float4*)(Bg + (size_t)(kt+1)*16*N);
            pb1 = *(const float4*)(Bg + (size_t)(kt+1)*16*N + 4);
        }
        /* compute 2 k-steps of 8 */
        #pragma unroll
        for (int ks = 0; ks < 2; ks++) {
            int kk = ks*8;
            uint32_t ah[2][4], al[2][4];
            #pragma unroll
            for (int i = 0; i < 2; i++) {
                int mb = warpM*32 + i*16;
                float r0 = As[(mb + g)*20     + kk + t];
                float r1 = As[(mb + g + 8)*20 + kk + t];
                float r2 = As[(mb + g)*20     + kk + t + 4];
                float r3 = As[(mb + g + 8)*20 + kk + t + 4];
                ah[i][0] = f2tf(r0); al[i][0] = f2tf(r0 - __uint_as_float(ah[i][0]));
                ah[i][1] = f2tf(r1); al[i][1] = f2tf(r1 - __uint_as_float(ah[i][1]));
                ah[i][2] = f2tf(r2); al[i][2] = f2tf(r2 - __uint_as_float(ah[i][2]));
                ah[i][3] = f2tf(r3); al[i][3] = f2tf(r3 - __uint_as_float(ah[i][3]));
            }
            #pragma unroll
            for (int j = 0; j < 8; j++) {
                int col = warpN*64 + j*8 + g;
                float s0 = Bs[(kk + t)*136     + col];
                float s1 = Bs[(kk + t + 4)*136 + col];
                uint32_t bh[2], bl[2];
                bh[0] = f2tf(s0); bl[0] = f2tf(s0 - __uint_as_float(bh[0]));
                bh[1] = f2tf(s1); bl[1] = f2tf(s1 - __uint_as_float(bh[1]));
                #pragma unroll
                for (int i = 0; i < 2; i++) {
                    mma_tf32(acc[i][j], ah[i], bh);
                    mma_tf32(acc[i][j], al[i], bh);
                    mma_tf32(acc[i][j], ah[i], bl);
                }
            }
        }
        __syncthreads();
    }

    /* epilogue */
    #pragma unroll
    for (int i = 0; i < 2; i++) {
        int r0 = bm*128 + warpM*32 + i*16 + g;
        #pragma unroll
        for (int j = 0; j < 8; j++) {
            int col = bn*128 + warpN*64 + j*8 + t*2;
            *(float2*)(g_xz + (size_t)r0*N + col)     = make_float2(acc[i][j][0], acc[i][j][1]);
            *(float2*)(g_xz + (size_t)(r0+8)*N + col) = make_float2(acc[i][j][2], acc[i][j][3]);
        }
    }
}

/* ------------- 3. causal depthwise conv (K=4) + SiLU ------------- */
__global__ __launch_bounds__(256) void conv_silu_kernel(const float* __restrict__ cw,
                                                        const float* __restrict__ cb) {
    int idx = blockIdx.x*256 + threadIdx.x;   /* over Rx*DIx */
    int d = idx % DIx;
    int row = idx / DIx;
    int t = row & (Lx-1);
    float w0 = cw[d*4+0], w1 = cw[d*4+1], w2 = cw[d*4+2], w3 = cw[d*4+3];
    float acc = cb[d];
    const float* xp = g_xz + (size_t)row*(2*DIx) + d;
    if (t >= 3) acc += w0 * xp[-(size_t)3*(2*DIx)];
    if (t >= 2) acc += w1 * xp[-(size_t)2*(2*DIx)];
    if (t >= 1) acc += w2 * xp[-(size_t)1*(2*DIx)];
    acc += w3 * xp[0];
    g_xc[(size_t)row*DIx + d] = siluf(acc);
}

/* ------------- 4. xproj: g_xc[32768,768] @ W_xproj[768,56] -> dtr/B/C ------------- */
__global__ __launch_bounds__(256) void xproj_kernel(const float* __restrict__ W) {
    __shared__ float As[32][128];
    __shared__ float Ws[32][56];
    int tid = threadIdx.x;
    int m0 = blockIdx.x * 128;
    int rm = (tid >> 3) * 4, cn = (tid & 7) * 7;
    float acc[4][7] = {};
    for (int k0 = 0; k0 < DIx; k0 += 32) {
        #pragma unroll
        for (int l = 0; l < 4; l++) {
            int f = tid + l*256;
            int r = f >> 3, c4 = (f & 7)*4;
            float4 v = *(const float4*)(g_xc + (size_t)(m0+r)*DIx + k0 + c4);
            As[c4+0][r] = v.x; As[c4+1][r] = v.y; As[c4+2][r] = v.z; As[c4+3][r] = v.w;
        }
        #pragma unroll
        for (int l = 0; l < 2; l++) {
            int f = tid + l*256;
            if (f < 448) {
                int kr = f / 14, c4 = (f % 14)*4;
                *(float4*)(&Ws[kr][c4]) = *(const float4*)(W + (size_t)(k0+kr)*56 + c4);
            }
        }
        __syncthreads();
        #pragma unroll
        for (int k = 0; k < 32; k++) {
            float ra[4], rw[7];
            #pragma unroll
            for (int i = 0; i < 4; i++) ra[i] = As[k][rm+i];
            #pragma unroll
            for (int j = 0; j < 7; j++) rw[j] = Ws[k][cn+j];
            #pragma unroll
            for (int i = 0; i < 4; i++)
                #pragma unroll
                for (int j = 0; j < 7; j++) acc[i][j] += ra[i]*rw[j];
        }
        __syncthreads();
    }
    #pragma unroll
    for (int i = 0; i < 4; i++)
        #pragma unroll
        for (int j = 0; j < 7; j++) {
            int cc = cn + j;
            size_t row = (size_t)(m0 + rm + i);
            float v = acc[i][j];
            if (cc < 24)       g_dtr[row*DTRx + cc] = v;
            else if (cc < 40)  g_Bmat[row*Sx + (cc-24)] = v;
            else               g_Cmat[row*Sx + (cc-40)] = v;
        }
}

/* ------------- 5. dt GEMM: g_dtr[32768,24] @ W_dt[24,768] + bias -> softplus ------------- */
__global__ __launch_bounds__(256) void dt_gemm_kernel(const float* __restrict__ Wdt,
                                                      const float* __restrict__ bias) {
    __shared__ float As[64][24];
    __shared__ float Ws[24][128];
    int tid = threadIdx.x;
    int n0 = blockIdx.x * 128, m0 = blockIdx.y * 64;
    #pragma unroll
    for (int l = 0; l < 2; l++) {
        int f = tid + l*256;
        if (f < 384) {
            int r = f / 6, c4 = (f % 6)*4;
            *(float4*)(&As[r][c4]) = *(const float4*)(g_dtr + (size_t)(m0+r)*DTRx + c4);
        }
    }
    #pragma unroll
    for (int l = 0; l < 3; l++) {
        int f = tid + l*256;
        int kr = f >> 5, c4 = (f & 31)*4;
        *(float4*)(&Ws[kr][c4]) = *(const float4*)(Wdt + (size_t)kr*DIx + n0 + c4);
    }
    __syncthreads();
    int rm = (tid >> 5)*8, cn = (tid & 31)*4;
    float acc[8][4] = {};
    #pragma unroll
    for (int k = 0; k < 24; k++) {
        float rw0 = Ws[k][cn], rw1 = Ws[k][cn+1], rw2 = Ws[k][cn+2], rw3 = Ws[k][cn+3];
        #pragma unroll
        for (int i = 0; i < 8; i++) {
            float a = As[rm+i][k];
            acc[i][0] += a*rw0; acc[i][1] += a*rw1; acc[i][2] += a*rw2; acc[i][3] += a*rw3;
        }
    }
    float b0 = bias[n0+cn], b1 = bias[n0+cn+1], b2 = bias[n0+cn+2], b3 = bias[n0+cn+3];
    #pragma unroll
    for (int i = 0; i < 8; i++) {
        float4 o;
        o.x = softplusf(acc[i][0] + b0);
        o.y = softplusf(acc[i][1] + b1);
        o.z = softplusf(acc[i][2] + b2);
        o.w = softplusf(acc[i][3] + b3);
        *(float4*)(g_dt + (size_t)(m0+rm+i)*DIx + n0 + cn) = o;
    }
}

/* ------------- 6. A = -exp(A_log) ------------- */
__global__ void prep_A_kernel(const float* __restrict__ A_log) {
    int i = blockIdx.x*256 + threadIdx.x;
    if (i < DIx*Sx) g_A[i] = -__expf(A_log[i]);
}

/* ------------- 7. scan pass1: per-chunk final state + dt-sum ------------- */
__global__ __launch_bounds__(128) void scan_pass1_kernel() {
    int d = blockIdx.x*128 + threadIdx.x;
    int c = blockIdx.y, b = blockIdx.z;
    float a[Sx], h[Sx];
    const float4* Ap = (const float4*)(g_A + d*Sx);
    #pragma unroll
    for (int q = 0; q < 4; q++) {
        float4 v = Ap[q];
        a[q*4+0] = v.x; a[q*4+1] = v.y; a[q*4+2] = v.z; a[q*4+3] = v.w;
    }
    #pragma unroll
    for (int s = 0; s < Sx; s++) h[s] = 0.f;
    float ds = 0.f;
    int row0 = b*Lx + c*CLEN;
    const float* dtp = g_dt + (size_t)row0*DIx + d;
    const float* xp  = g_xc + (size_t)row0*DIx + d;
    const float4* Bp = (const float4*)(g_Bmat + (size_t)row0*Sx);
    #pragma unroll 2
    for (int t = 0; t < CLEN; t++) {
        float dv = dtp[(size_t)t*DIx];
        float xv = xp[(size_t)t*DIx];
        float4 q0 = Bp[t*4+0], q1 = Bp[t*4+1], q2 = Bp[t*4+2], q3 = Bp[t*4+3];
        float Bv[16] = {q0.x,q0.y,q0.z,q0.w,q1.x,q1.y,q1.z,q1.w,
                        q2.x,q2.y,q2.z,q2.w,q3.x,q3.y,q3.z,q3.w};
        float c1 = dv*xv;
        ds += dv;
        #pragma unroll
        for (int s = 0; s < Sx; s++)
            h[s] = __expf(dv*a[s])*h[s] + c1*Bv[s];
    }
    size_t base = (((size_t)b*NCH + c)*DIx + d)*Sx;
    #pragma unroll
    for (int s = 0; s < Sx; s += 4)
        *(float4*)(g_hfin + base + s) = make_float4(h[s], h[s+1], h[s+2], h[s+3]);
    g_dtsum[(b*NCH + c)*DIx + d] = ds;
}

/* ------------- 8. sequential chunk combine ------------- */
__global__ __launch_bounds__(256) void scan_combine_kernel() {
    int gid = blockIdx.x*256 + threadIdx.x;  /* < 8*768*16 */
    int s = gid & 15;
    int d = (gid >> 4) % DIx;
    int b = gid / (DIx*Sx);
    float a = g_A[d*Sx + s];
    float H = 0.f;
    for (int c = 0; c < NCH; c++) {
        size_t idx = (((size_t)b*NCH + c)*DIx + d)*Sx + s;
        g_Hini[idx] = H;
        float ds = g_dtsum[(b*NCH + c)*DIx + d];
        H = __expf(a*ds)*H + g_hfin[idx];
    }
}

/* ------------- 9. scan pass2: full scan per chunk, emit y ------------- */
__global__ __launch_bounds__(128) void scan_pass2_kernel() {
    int d = blockIdx.x*128 + threadIdx.x;
    int c = blockIdx.y, b = blockIdx.z;
    float a[Sx], h[Sx];
    const float4* Ap = (const float4*)(g_A + d*Sx);
    #pragma unroll
    for (int q = 0; q < 4; q++) {
        float4 v = Ap[q];
        a[q*4+0] = v.x; a[q*4+1] = v.y; a[q*4+2] = v.z; a[q*4+3] = v.w;
    }
    size_t hbase = (((size_t)b*NCH + c)*DIx + d)*Sx;
    #pragma unroll
    for (int q = 0; q < 4; q++) {
        float4 v = *(const float4*)(g_Hini + hbase + q*4);
        h[q*4+0] = v.x; h[q*4+1] = v.y; h[q*4+2] = v.z; h[q*4+3] = v.w;
    }
    int row0 = b*Lx + c*CLEN;
    const float* dtp = g_dt + (size_t)row0*DIx + d;
    const float* xp  = g_xc + (size_t)row0*DIx + d;
    const float4* Bp = (const float4*)(g_Bmat + (size_t)row0*Sx);
    const float4* Cp = (const float4*)(g_Cmat + (size_t)row0*Sx);
    float* yp = g_yssm + (size_t)row0*DIx + d;
    #pragma unroll 2
    for (int t = 0; t < CLEN; t++) {
        float dv = dtp[(size_t)t*DIx];
        float xv = xp[(size_t)t*DIx];
        float4 q0 = Bp[t*4+0], q1 = Bp[t*4+1], q2 = Bp[t*4+2], q3 = Bp[t*4+3];
        float Bv[16] = {q0.x,q0.y,q0.z,q0.w,q1.x,q1.y,q1.z,q1.w,
                        q2.x,q2.y,q2.z,q2.w,q3.x,q3.y,q3.z,q3.w};
        float4 r0 = Cp[t*4+0], r1 = Cp[t*4+1], r2 = Cp[t*4+2], r3 = Cp[t*4+3];
        float Cv[16] = {r0.x,r0.y,r0.z,r0.w,r1.x,r1.y,r1.z,r1.w,
                        r2.x,r2.y,r2.z,r2.w,r3.x,r3.y,r3.z,r3.w};
        float c1 = dv*xv;
        float y = 0.f;
        #pragma unroll
        for (int s = 0; s < Sx; s++) {
            h[s] = __expf(dv*a[s])*h[s] + c1*Bv[s];
            y += h[s]*Cv[s];
        }
        yp[(size_t)t*DIx] = y;
    }
}

/* ------------- 10. mean over L of x (partials, deterministic) ------------- */
__global__ __launch_bounds__(384) void meanx_part_kernel(const float* __restrict__ x) {
    int b = blockIdx.x, cz = blockIdx.y, j = threadIdx.x;
    float acc = 0.f;
    for (int i = 0; i < 256; i++)
        acc += x[((size_t)b*Lx + cz*256 + i)*Dx + j];
    g_xpart[(b*16 + cz)*Dx + j] = acc;
}

/* ------------- 11. yv = (y + xc*Dskip)*silu(z) partial sums over L ------------- */
__global__ __launch_bounds__(256) void finalize_part_kernel(const float* __restrict__ Dskip) {
    int b = blockIdx.x, cc = blockIdx.y, tid = threadIdx.x;
    int t0 = cc*CLEN;
    int d0 = tid, d1 = tid+256, d2 = tid+512;
    float k0 = Dskip[d0], k1 = Dskip[d1], k2 = Dskip[d2];
    float a0 = 0.f, a1 = 0.f, a2 = 0.f;
    for (int i = 0; i < CLEN; i++) {
        size_t row = (size_t)b*Lx + t0 + i;
        const float* yr = g_yssm + row*DIx;
        const float* xr = g_xc + row*DIx;
        const float* zr = g_xz + row*(2*DIx) + DIx;
        float z0 = zr[d0], z1 = zr[d1], z2 = zr[d2];
        a0 += (yr[d0] + xr[d0]*k0) * siluf(z0);
        a1 += (yr[d1] + xr[d1]*k1) * siluf(z1);
        a2 += (yr[d2] + xr[d2]*k2) * siluf(z2);
    }
    g_yvpart[(b*NCH + cc)*DIx + d0] = a0;
    g_yvpart[(b*NCH + cc)*DIx + d1] = a1;
    g_yvpart[(b*NCH + cc)*DIx + d2] = a2;
}

/* ------------- 12. pooled = (sum_x + sum_yv @ W_out)/L ------------- */
__global__ __launch_bounds__(256) void pooled_gemm_kernel(const float* __restrict__ Wout) {
    __shared__ float myv[DIx];
    __shared__ float red[8][32];
    int tid = threadIdx.x;
    int b = blockIdx.x, j0 = blockIdx.y*32;
    for (int f = tid; f < DIx; f += 256) {
        float s = 0.f;
        #pragma unroll 4
        for (int cc = 0; cc < NCH; cc++) s += g_yvpart[(b*NCH + cc)*DIx + f];
        myv[f] = s;
    }
    __syncthreads();
    int j = j0 + (tid & 31), seg = tid >> 5;
    float acc = 0.f;
    for (int d = seg*96; d < seg*96 + 96; d++)
        acc += myv[d] * Wout[(size_t)d*Dx + j];
    red[seg][tid & 31] = acc;
    __syncthreads();
    if (seg == 0) {
        float tot = 0.f;
        #pragma unroll
        for (int s = 0; s < 8; s++) tot += red[s][tid];
        float mx = 0.f;
        #pragma unroll
        for (int cz = 0; cz < 16; cz++) mx += g_xpart[(b*16 + cz)*Dx + j];
        g_pooled[b*Dx + j] = (mx + tot) * (1.f/Lx);
    }
}

/* ------------- 13. fc: pooled[8,384] @ W_fc[384,256] + b_fc ------------- */
__global__ __launch_bounds__(256) void fc_kernel(const float* __restrict__ Wfc,
                                                 const float* __restrict__ bfc) {
    __shared__ float ps[Dx];
    int b = blockIdx.x, tid = threadIdx.x;
    for (int f = tid; f < Dx; f += 256) ps[f] = g_pooled[b*Dx + f];
    __syncthreads();
    float acc = bfc[tid];
    for (int jj = 0; jj < Dx; jj++) acc += ps[jj] * Wfc[(size_t)jj*256 + tid];
    g_hfc[b*256 + tid] = acc;
}

/* ------------- 14. head: batchnorm(8) + relu + cls ------------- */
__global__ __launch_bounds__(256) void head_kernel(const float* __restrict__ gamma,
                                                   const float* __restrict__ beta,
                                                   const float* __restrict__ Wcls,
                                                   const float* __restrict__ bcls,
                                                   float* __restrict__ out) {
    __shared__ float hs[Bx*256];
    int tid = threadIdx.x;
    for (int f = tid; f < Bx*256; f += 256) hs[f] = g_hfc[f];
    __syncthreads();
    int c = tid;
    float mu = 0.f;
    #pragma unroll
    for (int b = 0; b < Bx; b++) mu += hs[b*256 + c];
    mu *= 0.125f;
    float var = 0.f;
    #pragma unroll
    for (int b = 0; b < Bx; b++) { float dd = hs[b*256 + c] - mu; var += dd*dd; }
    var *= 0.125f;
    float inv = rsqrtf(var + 1e-5f);
    float ga = gamma[c], be = beta[c];
    #pragma unroll
    for (int b = 0; b < Bx; b++) {
        float v = (hs[b*256 + c] - mu)*inv*ga + be;
        hs[b*256 + c] = fmaxf(v, 0.f);
    }
    __syncthreads();
    for (int t = tid; t < Bx*40; t += 256) {
        int b = t / 40, n = t % 40;
        float acc = bcls[n];
        for (int c2 = 0; c2 < 256; c2++) acc += hs[b*256 + c2] * Wcls[c2*40 + n];
        out[t] = acc;
    }
}

/* ------------- launch ------------- */
extern "C" void kernel_launch(void* const* d_in, const int* in_sizes, int n_in,
                              void* d_out, int out_size) {
    const float* x       = (const float*)d_in[0];
    const float* ln_w    = (const float*)d_in[1];
    const float* W_in    = (const float*)d_in[2];
    const float* conv_w  = (const float*)d_in[3];
    const float* conv_b  = (const float*)d_in[4];
    const float* W_xproj = (const float*)d_in[5];
    const float* W_dt    = (const float*)d_in[6];
    const float* dt_bias = (const float*)d_in[7];
    const float* A_log   = (const float*)d_in[8];
    const float* Dskip   = (const float*)d_in[9];
    const float* W_out   = (const float*)d_in[10];
    const float* W_fc    = (const float*)d_in[11];
    const float* b_fc    = (const float*)d_in[12];
    const float* bn_g    = (const float*)d_in[13];
    const float* bn_b    = (const float*)d_in[14];
    const float* W_cls   = (const float*)d_in[15];
    const float* b_cls   = (const float*)d_in[16];
    float* out = (float*)d_out;

    rmsnorm_kernel<<<Rx, 128>>>(x, ln_w);
    gemm_in_tc_kernel<<<dim3(12, Rx/128), 256>>>(W_in);
    conv_silu_kernel<<<(Rx*DIx)/256, 256>>>(conv_w, conv_b);
    xproj_kernel<<<Rx/128, 256>>>(W_xproj);
    dt_gemm_kernel<<<dim3(6, Rx/64), 256>>>(W_dt, dt_bias);
    prep_A_kernel<<<48, 256>>>(A_log);
    scan_pass1_kernel<<<dim3(6, NCH, Bx), 128>>>();
    scan_combine_kernel<<<(Bx*DIx*Sx)/256, 256>>>();
    scan_pass2_kernel<<<dim3(6, NCH, Bx), 128>>>();
    meanx_part_kernel<<<dim3(Bx, 16), 384>>>(x);
    finalize_part_kernel<<<dim3(Bx, NCH), 256>>>(Dskip);
    pooled_gemm_kernel<<<dim3(Bx, 12), 256>>>(W_out);
    fc_kernel<<<Bx, 256>>>(W_fc, b_fc);
    head_kernel<<<1, 256>>>(bn_g, bn_b, W_cls, b_cls, out);
}

// round 4
// speedup vs baseline: 1.7615x; 1.7615x over previous
#include <cuda_runtime.h>
#include <cuda_bf16.h>
#include <math.h>
#include <stdint.h>

#define Bx   8
#define Lx   4096
#define Dx   384
#define DIx  768
#define Sx   16
#define DTRx 24
#define Rx   (Bx*Lx)        /* 32768 rows */
#define NCH  32
#define CLEN (Lx/NCH)       /* 128 */
#define KEXP 1152           /* 3*Dx expanded K */

/* ------------- device scratch (static, no allocations) ------------- */
__device__ __align__(128) __nv_bfloat16 g_Abf[(size_t)Rx*KEXP];
__device__ __align__(128) __nv_bfloat16 g_Bt [(size_t)2*DIx*KEXP];
__device__ __align__(128) float g_xz [(size_t)Rx*2*DIx];
__device__ __align__(128) float g_xc [(size_t)Rx*DIx];
__device__ __align__(128) float g_dtr[(size_t)Rx*DTRx];
__device__ __align__(128) float g_Bmat[(size_t)Rx*Sx];
__device__ __align__(128) float g_Cmat[(size_t)Rx*Sx];
__device__ __align__(128) float g_dt [(size_t)Rx*DIx];
__device__ __align__(128) float g_yssm[(size_t)Rx*DIx];
__device__ __align__(128) float g_A  [DIx*Sx];
__device__ __align__(128) float g_hfin[(size_t)Bx*NCH*DIx*Sx];
__device__ __align__(128) float g_Hini[(size_t)Bx*NCH*DIx*Sx];
__device__ __align__(128) float g_dtsum[Bx*NCH*DIx];
__device__ __align__(128) float g_yvpart[Bx*NCH*DIx];
__device__ __align__(128) float g_xpart[Bx*16*Dx];
__device__ __align__(128) float g_pooled[Bx*Dx];
__device__ __align__(128) float g_hfc[Bx*256];

__device__ __forceinline__ float softplusf(float v) {
    return v > 20.f ? v : log1pf(__expf(v));
}
__device__ __forceinline__ float siluf(float v) {
    return v / (1.f + __expf(-v));
}

/* ------------- 1. RMSNorm -> split-bf16 A' = [hi | lo | hi] ------------- */
__global__ __launch_bounds__(128) void rmsnorm_kernel(const float* __restrict__ x,
                                                      const float* __restrict__ w) {
    int row = blockIdx.x, tid = threadIdx.x;
    const float* xr = x + (size_t)row*Dx;
    float v0 = xr[tid], v1 = xr[tid+128], v2 = xr[tid+256];
    float ss = v0*v0 + v1*v1 + v2*v2;
    #pragma unroll
    for (int o = 16; o; o >>= 1) ss += __shfl_xor_sync(0xffffffffu, ss, o);
    __shared__ float sm[4];
    if ((tid & 31) == 0) sm[tid >> 5] = ss;
    __syncthreads();
    float tot = sm[0] + sm[1] + sm[2] + sm[3];
    float sc  = rsqrtf(tot * (1.f/Dx) + 1e-5f);
    __nv_bfloat16* o = g_Abf + (size_t)row*KEXP;
    float ys[3] = { v0*sc*w[tid], v1*sc*w[tid+128], v2*sc*w[tid+256] };
    int cs[3] = { tid, tid+128, tid+256 };
    #pragma unroll
    for (int q = 0; q < 3; q++) {
        __nv_bfloat16 h = __float2bfloat16(ys[q]);
        __nv_bfloat16 l = __float2bfloat16(ys[q] - __bfloat162float(h));
        o[cs[q]]       = h;
        o[384 + cs[q]] = l;
        o[768 + cs[q]] = h;
    }
}

/* ------------- 1b. build B'^T [1536][1152] = [hi | hi | lo] of W_in^T ------------- */
__global__ __launch_bounds__(256) void prepB_kernel(const float* __restrict__ W) {
    int k = blockIdx.x;  /* 0..383 */
    for (int n = threadIdx.x; n < 2*DIx; n += 256) {
        float v = W[(size_t)k*(2*DIx) + n];
        __nv_bfloat16 h = __float2bfloat16(v);
        __nv_bfloat16 l = __float2bfloat16(v - __bfloat162float(h));
        g_Bt[(size_t)n*KEXP + k]       = h;
        g_Bt[(size_t)n*KEXP + 384 + k] = h;
        g_Bt[(size_t)n*KEXP + 768 + k] = l;
    }
}

/* ------------- 2. GEMM1 bf16 TC: g_Abf[32768,1152] @ g_Bt^T -> g_xz[32768,1536] ------------- */
__device__ __forceinline__ void cp16(uint32_t dst, const void* src) {
    asm volatile("cp.async.cg.shared.global [%0], [%1], 16;\n" :: "r"(dst), "l"(src));
}
__device__ __forceinline__ void cp_commit() {
    asm volatile("cp.async.commit_group;\n");
}
template<int N> __device__ __forceinline__ void cp_wait() {
    asm volatile("cp.async.wait_group %0;\n" :: "n"(N));
}
__device__ __forceinline__ void mma_bf16(float* c, const uint32_t* a, uint32_t b0, uint32_t b1) {
    asm volatile("mma.sync.aligned.m16n8k16.row.col.f32.bf16.bf16.f32 "
        "{%0,%1,%2,%3}, {%4,%5,%6,%7}, {%8,%9}, {%0,%1,%2,%3};\n"
        : "+f"(c[0]), "+f"(c[1]), "+f"(c[2]), "+f"(c[3])
        : "r"(a[0]), "r"(a[1]), "r"(a[2]), "r"(a[3]), "r"(b0), "r"(b1));
}

#define LDP 40            /* padded row: 32 data + 8 pad bf16 */
#define TILEB (128*LDP)   /* elements per buffer */
#define NKT 36            /* 1152/32 */

__global__ __launch_bounds__(256) void gemm_bf16_kernel() {
    const int N = 2*DIx;
    __shared__ __align__(16) __nv_bfloat16 As[2][TILEB];
    __shared__ __align__(16) __nv_bfloat16 Bs[2][TILEB];
    int tid = threadIdx.x;
    int lane = tid & 31, warp = tid >> 5;
    int warpM = warp >> 1, warpN = warp & 1;
    int bn = blockIdx.x, bm = blockIdx.y;
    int g = lane >> 2, t = lane & 3;

    int lr = tid >> 2;       /* 0..63 loader row */
    int lc = tid & 3;        /* 16B chunk */
    const __nv_bfloat16* Asrc0 = g_Abf + (size_t)(bm*128 + lr)*KEXP + lc*8;
    const __nv_bfloat16* Asrc1 = Asrc0 + (size_t)64*KEXP;
    const __nv_bfloat16* Bsrc0 = g_Bt  + (size_t)(bn*128 + lr)*KEXP + lc*8;
    const __nv_bfloat16* Bsrc1 = Bsrc0 + (size_t)64*KEXP;
    uint32_t a_d0 = (uint32_t)__cvta_generic_to_shared(&As[0][lr*LDP + lc*8]);
    uint32_t a_d1 = (uint32_t)__cvta_generic_to_shared(&As[0][(64+lr)*LDP + lc*8]);
    uint32_t b_d0 = (uint32_t)__cvta_generic_to_shared(&Bs[0][lr*LDP + lc*8]);
    uint32_t b_d1 = (uint32_t)__cvta_generic_to_shared(&Bs[0][(64+lr)*LDP + lc*8]);
    const uint32_t BUFB = TILEB*2;  /* bytes per buffer */

    float acc[2][8][4];
    #pragma unroll
    for (int i = 0; i < 2; i++)
        #pragma unroll
        for (int j = 0; j < 8; j++)
            #pragma unroll
            for (int q = 0; q < 4; q++) acc[i][j][q] = 0.f;

    /* prologue fill tile 0 */
    cp16(a_d0, Asrc0); cp16(a_d1, Asrc1);
    cp16(b_d0, Bsrc0); cp16(b_d1, Bsrc1);
    cp_commit();

    for (int kt = 0; kt < NKT; kt++) {
        int buf = kt & 1;
        if (kt + 1 < NKT) {
            uint32_t off = (buf ^ 1) * BUFB;
            const __nv_bfloat16* ap0 = Asrc0 + (kt+1)*32;
            cp16(a_d0 + off, ap0);
            cp16(a_d1 + off, Asrc1 + (kt+1)*32);
            cp16(b_d0 + off, Bsrc0 + (kt+1)*32);
            cp16(b_d1 + off, Bsrc1 + (kt+1)*32);
            cp_commit();
            cp_wait<1>();
        } else {
            cp_commit();
            cp_wait<0>();
        }
        __syncthreads();
        const __nv_bfloat16* A_s = As[buf];
        const __nv_bfloat16* B_s = Bs[buf];
        #pragma unroll
        for (int ks = 0; ks < 2; ks++) {
            int kk = ks*16 + t*2;
            uint32_t af[2][4];
            #pragma unroll
            for (int i = 0; i < 2; i++) {
                int m0 = warpM*32 + i*16;
                af[i][0] = *(const uint32_t*)&A_s[(m0+g)*LDP   + kk];
                af[i][1] = *(const uint32_t*)&A_s[(m0+g+8)*LDP + kk];
                af[i][2] = *(const uint32_t*)&A_s[(m0+g)*LDP   + kk + 8];
                af[i][3] = *(const uint32_t*)&A_s[(m0+g+8)*LDP + kk + 8];
            }
            #pragma unroll
            for (int j = 0; j < 8; j++) {
                int n = warpN*64 + j*8 + g;
                uint32_t b0 = *(const uint32_t*)&B_s[n*LDP + kk];
                uint32_t b1 = *(const uint32_t*)&B_s[n*LDP + kk + 8];
                mma_bf16(acc[0][j], af[0], b0, b1);
                mma_bf16(acc[1][j], af[1], b0, b1);
            }
        }
        __syncthreads();
    }

    /* epilogue */
    #pragma unroll
    for (int i = 0; i < 2; i++) {
        int r0 = bm*128 + warpM*32 + i*16 + g;
        #pragma unroll
        for (int j = 0; j < 8; j++) {
            int col = bn*128 + warpN*64 + j*8 + t*2;
            *(float2*)(g_xz + (size_t)r0*N + col)     = make_float2(acc[i][j][0], acc[i][j][1]);
            *(float2*)(g_xz + (size_t)(r0+8)*N + col) = make_float2(acc[i][j][2], acc[i][j][3]);
        }
    }
}

/* ------------- 3. causal depthwise conv (K=4) + SiLU ------------- */
__global__ __launch_bounds__(256) void conv_silu_kernel(const float* __restrict__ cw,
                                                        const float* __restrict__ cb) {
    int idx = blockIdx.x*256 + threadIdx.x;   /* over Rx*DIx */
    int d = idx % DIx;
    int row = idx / DIx;
    int t = row & (Lx-1);
    float w0 = cw[d*4+0], w1 = cw[d*4+1], w2 = cw[d*4+2], w3 = cw[d*4+3];
    float acc = cb[d];
    const float* xp = g_xz + (size_t)row*(2*DIx) + d;
    if (t >= 3) acc += w0 * xp[-(size_t)3*(2*DIx)];
    if (t >= 2) acc += w1 * xp[-(size_t)2*(2*DIx)];
    if (t >= 1) acc += w2 * xp[-(size_t)1*(2*DIx)];
    acc += w3 * xp[0];
    g_xc[(size_t)row*DIx + d] = siluf(acc);
}

/* ------------- 4. xproj: g_xc[32768,768] @ W_xproj[768,56] -> dtr/B/C ------------- */
__global__ __launch_bounds__(256) void xproj_kernel(const float* __restrict__ W) {
    __shared__ float As[32][128];
    __shared__ float Ws[32][56];
    int tid = threadIdx.x;
    int m0 = blockIdx.x * 128;
    int rm = (tid >> 3) * 4, cn = (tid & 7) * 7;
    float acc[4][7] = {};
    for (int k0 = 0; k0 < DIx; k0 += 32) {
        #pragma unroll
        for (int l = 0; l < 4; l++) {
            int f = tid + l*256;
            int r = f >> 3, c4 = (f & 7)*4;
            float4 v = *(const float4*)(g_xc + (size_t)(m0+r)*DIx + k0 + c4);
            As[c4+0][r] = v.x; As[c4+1][r] = v.y; As[c4+2][r] = v.z; As[c4+3][r] = v.w;
        }
        #pragma unroll
        for (int l = 0; l < 2; l++) {
            int f = tid + l*256;
            if (f < 448) {
                int kr = f / 14, c4 = (f % 14)*4;
                *(float4*)(&Ws[kr][c4]) = *(const float4*)(W + (size_t)(k0+kr)*56 + c4);
            }
        }
        __syncthreads();
        #pragma unroll
        for (int k = 0; k < 32; k++) {
            float ra[4], rw[7];
            #pragma unroll
            for (int i = 0; i < 4; i++) ra[i] = As[k][rm+i];
            #pragma unroll
            for (int j = 0; j < 7; j++) rw[j] = Ws[k][cn+j];
            #pragma unroll
            for (int i = 0; i < 4; i++)
                #pragma unroll
                for (int j = 0; j < 7; j++) acc[i][j] += ra[i]*rw[j];
        }
        __syncthreads();
    }
    #pragma unroll
    for (int i = 0; i < 4; i++)
        #pragma unroll
        for (int j = 0; j < 7; j++) {
            int cc = cn + j;
            size_t row = (size_t)(m0 + rm + i);
            float v = acc[i][j];
            if (cc < 24)       g_dtr[row*DTRx + cc] = v;
            else if (cc < 40)  g_Bmat[row*Sx + (cc-24)] = v;
            else               g_Cmat[row*Sx + (cc-40)] = v;
        }
}

/* ------------- 5. dt GEMM: g_dtr[32768,24] @ W_dt[24,768] + bias -> softplus ------------- */
__global__ __launch_bounds__(256) void dt_gemm_kernel(const float* __restrict__ Wdt,
                                                      const float* __restrict__ bias) {
    __shared__ float As[64][24];
    __shared__ float Ws[24][128];
    int tid = threadIdx.x;
    int n0 = blockIdx.x * 128, m0 = blockIdx.y * 64;
    #pragma unroll
    for (int l = 0; l < 2; l++) {
        int f = tid + l*256;
        if (f < 384) {
            int r = f / 6, c4 = (f % 6)*4;
            *(float4*)(&As[r][c4]) = *(const float4*)(g_dtr + (size_t)(m0+r)*DTRx + c4);
        }
    }
    #pragma unroll
    for (int l = 0; l < 3; l++) {
        int f = tid + l*256;
        int kr = f >> 5, c4 = (f & 31)*4;
        *(float4*)(&Ws[kr][c4]) = *(const float4*)(Wdt + (size_t)kr*DIx + n0 + c4);
    }
    __syncthreads();
    int rm = (tid >> 5)*8, cn = (tid & 31)*4;
    float acc[8][4] = {};
    #pragma unroll
    for (int k = 0; k < 24; k++) {
        float rw0 = Ws[k][cn], rw1 = Ws[k][cn+1], rw2 = Ws[k][cn+2], rw3 = Ws[k][cn+3];
        #pragma unroll
        for (int i = 0; i < 8; i++) {
            float a = As[rm+i][k];
            acc[i][0] += a*rw0; acc[i][1] += a*rw1; acc[i][2] += a*rw2; acc[i][3] += a*rw3;
        }
    }
    float b0 = bias[n0+cn], b1 = bias[n0+cn+1], b2 = bias[n0+cn+2], b3 = bias[n0+cn+3];
    #pragma unroll
    for (int i = 0; i < 8; i++) {
        float4 o;
        o.x = softplusf(acc[i][0] + b0);
        o.y = softplusf(acc[i][1] + b1);
        o.z = softplusf(acc[i][2] + b2);
        o.w = softplusf(acc[i][3] + b3);
        *(float4*)(g_dt + (size_t)(m0+rm+i)*DIx + n0 + cn) = o;
    }
}

/* ------------- 6. A = -exp(A_log) ------------- */
__global__ void prep_A_kernel(const float* __restrict__ A_log) {
    int i = blockIdx.x*256 + threadIdx.x;
    if (i < DIx*Sx) g_A[i] = -__expf(A_log[i]);
}

/* ------------- 7. scan pass1: per-chunk final state + dt-sum ------------- */
__global__ __launch_bounds__(128) void scan_pass1_kernel() {
    int d = blockIdx.x*128 + threadIdx.x;
    int c = blockIdx.y, b = blockIdx.z;
    float a[Sx], h[Sx];
    const float4* Ap = (const float4*)(g_A + d*Sx);
    #pragma unroll
    for (int q = 0; q < 4; q++) {
        float4 v = Ap[q];
        a[q*4+0] = v.x; a[q*4+1] = v.y; a[q*4+2] = v.z; a[q*4+3] = v.w;
    }
    #pragma unroll
    for (int s = 0; s < Sx; s++) h[s] = 0.f;
    float ds = 0.f;
    int row0 = b*Lx + c*CLEN;
    const float* dtp = g_dt + (size_t)row0*DIx + d;
    const float* xp  = g_xc + (size_t)row0*DIx + d;
    const float4* Bp = (const float4*)(g_Bmat + (size_t)row0*Sx);
    #pragma unroll 2
    for (int t = 0; t < CLEN; t++) {
        float dv = dtp[(size_t)t*DIx];
        float xv = xp[(size_t)t*DIx];
        float4 q0 = Bp[t*4+0], q1 = Bp[t*4+1], q2 = Bp[t*4+2], q3 = Bp[t*4+3];
        float Bv[16] = {q0.x,q0.y,q0.z,q0.w,q1.x,q1.y,q1.z,q1.w,
                        q2.x,q2.y,q2.z,q2.w,q3.x,q3.y,q3.z,q3.w};
        float c1 = dv*xv;
        ds += dv;
        #pragma unroll
        for (int s = 0; s < Sx; s++)
            h[s] = __expf(dv*a[s])*h[s] + c1*Bv[s];
    }
    size_t base = (((size_t)b*NCH + c)*DIx + d)*Sx;
    #pragma unroll
    for (int s = 0; s < Sx; s += 4)
        *(float4*)(g_hfin + base + s) = make_float4(h[s], h[s+1], h[s+2], h[s+3]);
    g_dtsum[(b*NCH + c)*DIx + d] = ds;
}

/* ------------- 8. sequential chunk combine ------------- */
__global__ __launch_bounds__(256) void scan_combine_kernel() {
    int gid = blockIdx.x*256 + threadIdx.x;  /* < 8*768*16 */
    int s = gid & 15;
    int d = (gid >> 4) % DIx;
    int b = gid / (DIx*Sx);
    float a = g_A[d*Sx + s];
    float H = 0.f;
    for (int c = 0; c < NCH; c++) {
        size_t idx = (((size_t)b*NCH + c)*DIx + d)*Sx + s;
        g_Hini[idx] = H;
        float ds = g_dtsum[(b*NCH + c)*DIx + d];
        H = __expf(a*ds)*H + g_hfin[idx];
    }
}

/* ------------- 9. scan pass2: full scan per chunk, emit y ------------- */
__global__ __launch_bounds__(128) void scan_pass2_kernel() {
    int d = blockIdx.x*128 + threadIdx.x;
    int c = blockIdx.y, b = blockIdx.z;
    float a[Sx], h[Sx];
    const float4* Ap = (const float4*)(g_A + d*Sx);
    #pragma unroll
    for (int q = 0; q < 4; q++) {
        float4 v = Ap[q];
        a[q*4+0] = v.x; a[q*4+1] = v.y; a[q*4+2] = v.z; a[q*4+3] = v.w;
    }
    size_t hbase = (((size_t)b*NCH + c)*DIx + d)*Sx;
    #pragma unroll
    for (int q = 0; q < 4; q++) {
        float4 v = *(const float4*)(g_Hini + hbase + q*4);
        h[q*4+0] = v.x; h[q*4+1] = v.y; h[q*4+2] = v.z; h[q*4+3] = v.w;
    }
    int row0 = b*Lx + c*CLEN;
    const float* dtp = g_dt + (size_t)row0*DIx + d;
    const float* xp  = g_xc + (size_t)row0*DIx + d;
    const float4* Bp = (const float4*)(g_Bmat + (size_t)row0*Sx);
    const float4* Cp = (const float4*)(g_Cmat + (size_t)row0*Sx);
    float* yp = g_yssm + (size_t)row0*DIx + d;
    #pragma unroll 2
    for (int t = 0; t < CLEN; t++) {
        float dv = dtp[(size_t)t*DIx];
        float xv = xp[(size_t)t*DIx];
        float4 q0 = Bp[t*4+0], q1 = Bp[t*4+1], q2 = Bp[t*4+2], q3 = Bp[t*4+3];
        float Bv[16] = {q0.x,q0.y,q0.z,q0.w,q1.x,q1.y,q1.z,q1.w,
                        q2.x,q2.y,q2.z,q2.w,q3.x,q3.y,q3.z,q3.w};
        float4 r0 = Cp[t*4+0], r1 = Cp[t*4+1], r2 = Cp[t*4+2], r3 = Cp[t*4+3];
        float Cv[16] = {r0.x,r0.y,r0.z,r0.w,r1.x,r1.y,r1.z,r1.w,
                        r2.x,r2.y,r2.z,r2.w,r3.x,r3.y,r3.z,r3.w};
        float c1 = dv*xv;
        float y = 0.f;
        #pragma unroll
        for (int s = 0; s < Sx; s++) {
            h[s] = __expf(dv*a[s])*h[s] + c1*Bv[s];
            y += h[s]*Cv[s];
        }
        yp[(size_t)t*DIx] = y;
    }
}

/* ------------- 10. mean over L of x (partials, deterministic) ------------- */
__global__ __launch_bounds__(384) void meanx_part_kernel(const float* __restrict__ x) {
    int b = blockIdx.x, cz = blockIdx.y, j = threadIdx.x;
    float acc = 0.f;
    for (int i = 0; i < 256; i++)
        acc += x[((size_t)b*Lx + cz*256 + i)*Dx + j];
    g_xpart[(b*16 + cz)*Dx + j] = acc;
}

/* ------------- 11. yv = (y + xc*Dskip)*silu(z) partial sums over L ------------- */
__global__ __launch_bounds__(256) void finalize_part_kernel(const float* __restrict__ Dskip) {
    int b = blockIdx.x, cc = blockIdx.y, tid = threadIdx.x;
    int t0 = cc*CLEN;
    int d0 = tid, d1 = tid+256, d2 = tid+512;
    float k0 = Dskip[d0], k1 = Dskip[d1], k2 = Dskip[d2];
    float a0 = 0.f, a1 = 0.f, a2 = 0.f;
    for (int i = 0; i < CLEN; i++) {
        size_t row = (size_t)b*Lx + t0 + i;
        const float* yr = g_yssm + row*DIx;
        const float* xr = g_xc + row*DIx;
        const float* zr = g_xz + row*(2*DIx) + DIx;
        float z0 = zr[d0], z1 = zr[d1], z2 = zr[d2];
        a0 += (yr[d0] + xr[d0]*k0) * siluf(z0);
        a1 += (yr[d1] + xr[d1]*k1) * siluf(z1);
        a2 += (yr[d2] + xr[d2]*k2) * siluf(z2);
    }
    g_yvpart[(b*NCH + cc)*DIx + d0] = a0;
    g_yvpart[(b*NCH + cc)*DIx + d1] = a1;
    g_yvpart[(b*NCH + cc)*DIx + d2] = a2;
}

/* ------------- 12. pooled = (sum_x + sum_yv @ W_out)/L ------------- */
__global__ __launch_bounds__(256) void pooled_gemm_kernel(const float* __restrict__ Wout) {
    __shared__ float myv[DIx];
    __shared__ float red[8][32];
    int tid = threadIdx.x;
    int b = blockIdx.x, j0 = blockIdx.y*32;
    for (int f = tid; f < DIx; f += 256) {
        float s = 0.f;
        #pragma unroll 4
        for (int cc = 0; cc < NCH; cc++) s += g_yvpart[(b*NCH + cc)*DIx + f];
        myv[f] = s;
    }
    __syncthreads();
    int j = j0 + (tid & 31), seg = tid >> 5;
    float acc = 0.f;
    for (int d = seg*96; d < seg*96 + 96; d++)
        acc += myv[d] * Wout[(size_t)d*Dx + j];
    red[seg][tid & 31] = acc;
    __syncthreads();
    if (seg == 0) {
        float tot = 0.f;
        #pragma unroll
        for (int s = 0; s < 8; s++) tot += red[s][tid];
        float mx = 0.f;
        #pragma unroll
        for (int cz = 0; cz < 16; cz++) mx += g_xpart[(b*16 + cz)*Dx + j];
        g_pooled[b*Dx + j] = (mx + tot) * (1.f/Lx);
    }
}

/* ------------- 13. fc: pooled[8,384] @ W_fc[384,256] + b_fc ------------- */
__global__ __launch_bounds__(256) void fc_kernel(const float* __restrict__ Wfc,
                                                 const float* __restrict__ bfc) {
    __shared__ float ps[Dx];
    int b = blockIdx.x, tid = threadIdx.x;
    for (int f = tid; f < Dx; f += 256) ps[f] = g_pooled[b*Dx + f];
    __syncthreads();
    float acc = bfc[tid];
    for (int jj = 0; jj < Dx; jj++) acc += ps[jj] * Wfc[(size_t)jj*256 + tid];
    g_hfc[b*256 + tid] = acc;
}

/* ------------- 14. head: batchnorm(8) + relu + cls ------------- */
__global__ __launch_bounds__(256) void head_kernel(const float* __restrict__ gamma,
                                                   const float* __restrict__ beta,
                                                   const float* __restrict__ Wcls,
                                                   const float* __restrict__ bcls,
                                                   float* __restrict__ out) {
    __shared__ float hs[Bx*256];
    int tid = threadIdx.x;
    for (int f = tid; f < Bx*256; f += 256) hs[f] = g_hfc[f];
    __syncthreads();
    int c = tid;
    float mu = 0.f;
    #pragma unroll
    for (int b = 0; b < Bx; b++) mu += hs[b*256 + c];
    mu *= 0.125f;
    float var = 0.f;
    #pragma unroll
    for (int b = 0; b < Bx; b++) { float dd = hs[b*256 + c] - mu; var += dd*dd; }
    var *= 0.125f;
    float inv = rsqrtf(var + 1e-5f);
    float ga = gamma[c], be = beta[c];
    #pragma unroll
    for (int b = 0; b < Bx; b++) {
        float v = (hs[b*256 + c] - mu)*inv*ga + be;
        hs[b*256 + c] = fmaxf(v, 0.f);
    }
    __syncthreads();
    for (int t = tid; t < Bx*40; t += 256) {
        int b = t / 40, n = t % 40;
        float acc = bcls[n];
        for (int c2 = 0; c2 < 256; c2++) acc += hs[b*256 + c2] * Wcls[c2*40 + n];
        out[t] = acc;
    }
}

/* ------------- launch ------------- */
extern "C" void kernel_launch(void* const* d_in, const int* in_sizes, int n_in,
                              void* d_out, int out_size) {
    const float* x       = (const float*)d_in[0];
    const float* ln_w    = (const float*)d_in[1];
    const float* W_in    = (const float*)d_in[2];
    const float* conv_w  = (const float*)d_in[3];
    const float* conv_b  = (const float*)d_in[4];
    const float* W_xproj = (const float*)d_in[5];
    const float* W_dt    = (const float*)d_in[6];
    const float* dt_bias = (const float*)d_in[7];
    const float* A_log   = (const float*)d_in[8];
    const float* Dskip   = (const float*)d_in[9];
    const float* W_out   = (const float*)d_in[10];
    const float* W_fc    = (const float*)d_in[11];
    const float* b_fc    = (const float*)d_in[12];
    const float* bn_g    = (const float*)d_in[13];
    const float* bn_b    = (const float*)d_in[14];
    const float* W_cls   = (const float*)d_in[15];
    const float* b_cls   = (const float*)d_in[16];
    float* out = (float*)d_out;

    rmsnorm_kernel<<<Rx, 128>>>(x, ln_w);
    prepB_kernel<<<Dx, 256>>>(W_in);
    gemm_bf16_kernel<<<dim3(12, Rx/128), 256>>>();
    conv_silu_kernel<<<(Rx*DIx)/256, 256>>>(conv_w, conv_b);
    xproj_kernel<<<Rx/128, 256>>>(W_xproj);
    dt_gemm_kernel<<<dim3(6, Rx/64), 256>>>(W_dt, dt_bias);
    prep_A_kernel<<<48, 256>>>(A_log);
    scan_pass1_kernel<<<dim3(6, NCH, Bx), 128>>>();
    scan_combine_kernel<<<(Bx*DIx*Sx)/256, 256>>>();
    scan_pass2_kernel<<<dim3(6, NCH, Bx), 128>>>();
    meanx_part_kernel<<<dim3(Bx, 16), 384>>>(x);
    finalize_part_kernel<<<dim3(Bx, NCH), 256>>>(Dskip);
    pooled_gemm_kernel<<<dim3(Bx, 12), 256>>>(W_out);
    fc_kernel<<<Bx, 256>>>(W_fc, b_fc);
    head_kernel<<<1, 256>>>(bn_g, bn_b, W_cls, b_cls, out);
}

// round 6
// speedup vs baseline: 2.0010x; 1.1360x over previous
#include <cuda_runtime.h>
#include <cuda_bf16.h>
#include <math.h>
#include <stdint.h>

#define Bx   8
#define Lx   4096
#define Dx   384
#define DIx  768
#define Sx   16
#define DTRx 24
#define Rx   (Bx*Lx)        /* 32768 rows */
#define NCH  32
#define CLEN (Lx/NCH)       /* 128 */
#define KEXP 1152           /* 3*Dx expanded K */

/* ------------- device scratch (static, no allocations) ------------- */
__device__ __align__(128) __nv_bfloat16 g_Abf[(size_t)Rx*KEXP];
__device__ __align__(128) __nv_bfloat16 g_Bt [(size_t)2*DIx*KEXP];
__device__ __align__(128) float g_xz [(size_t)Rx*2*DIx];
__device__ __align__(128) float g_xc [(size_t)Rx*DIx];
__device__ __align__(128) float g_dtr[(size_t)Rx*DTRx];
__device__ __align__(128) float g_Bmat[(size_t)Rx*Sx];
__device__ __align__(128) float g_Cmat[(size_t)Rx*Sx];
__device__ __align__(128) float g_dt [(size_t)Rx*DIx];
__device__ __align__(128) float g_A  [DIx*Sx];
__device__ __align__(128) float g_hfin[(size_t)Bx*NCH*DIx*Sx];
__device__ __align__(128) float g_Hini[(size_t)Bx*NCH*DIx*Sx];
__device__ __align__(128) float g_dtsum[Bx*NCH*DIx];
__device__ __align__(128) float g_yvpart[Bx*NCH*DIx];
__device__ __align__(128) float g_xpart[Bx*16*Dx];
__device__ __align__(128) float g_pooled[Bx*Dx];
__device__ __align__(128) float g_hfc[Bx*256];

__device__ __forceinline__ float softplusf(float v) {
    return v > 20.f ? v : log1pf(__expf(v));
}
__device__ __forceinline__ float siluf(float v) {
    return v / (1.f + __expf(-v));
}

/* ------------- 1. RMSNorm -> split-bf16 A' = [hi | lo | hi] ------------- */
__global__ __launch_bounds__(128) void rmsnorm_kernel(const float* __restrict__ x,
                                                      const float* __restrict__ w) {
    int row = blockIdx.x, tid = threadIdx.x;
    const float* xr = x + (size_t)row*Dx;
    float v0 = xr[tid], v1 = xr[tid+128], v2 = xr[tid+256];
    float ss = v0*v0 + v1*v1 + v2*v2;
    #pragma unroll
    for (int o = 16; o; o >>= 1) ss += __shfl_xor_sync(0xffffffffu, ss, o);
    __shared__ float sm[4];
    if ((tid & 31) == 0) sm[tid >> 5] = ss;
    __syncthreads();
    float tot = sm[0] + sm[1] + sm[2] + sm[3];
    float sc  = rsqrtf(tot * (1.f/Dx) + 1e-5f);
    __nv_bfloat16* o = g_Abf + (size_t)row*KEXP;
    float ys[3] = { v0*sc*w[tid], v1*sc*w[tid+128], v2*sc*w[tid+256] };
    int cs[3] = { tid, tid+128, tid+256 };
    #pragma unroll
    for (int q = 0; q < 3; q++) {
        __nv_bfloat16 h = __float2bfloat16(ys[q]);
        __nv_bfloat16 l = __float2bfloat16(ys[q] - __bfloat162float(h));
        o[cs[q]]       = h;
        o[384 + cs[q]] = l;
        o[768 + cs[q]] = h;
    }
}

/* ------------- 1b. build B'^T [1536][1152] = [hi | hi | lo] of W_in^T ------------- */
__global__ __launch_bounds__(256) void prepB_kernel(const float* __restrict__ W) {
    int k = blockIdx.x;  /* 0..383 */
    for (int n = threadIdx.x; n < 2*DIx; n += 256) {
        float v = W[(size_t)k*(2*DIx) + n];
        __nv_bfloat16 h = __float2bfloat16(v);
        __nv_bfloat16 l = __float2bfloat16(v - __bfloat162float(h));
        g_Bt[(size_t)n*KEXP + k]       = h;
        g_Bt[(size_t)n*KEXP + 384 + k] = h;
        g_Bt[(size_t)n*KEXP + 768 + k] = l;
    }
}

/* ------------- 2. GEMM1 bf16 TC ------------- */
__device__ __forceinline__ void cp16(uint32_t dst, const void* src) {
    asm volatile("cp.async.cg.shared.global [%0], [%1], 16;\n" :: "r"(dst), "l"(src));
}
__device__ __forceinline__ void cp_commit() {
    asm volatile("cp.async.commit_group;\n");
}
template<int N> __device__ __forceinline__ void cp_wait() {
    asm volatile("cp.async.wait_group %0;\n" :: "n"(N));
}
__device__ __forceinline__ void mma_bf16(float* c, const uint32_t* a, uint32_t b0, uint32_t b1) {
    asm volatile("mma.sync.aligned.m16n8k16.row.col.f32.bf16.bf16.f32 "
        "{%0,%1,%2,%3}, {%4,%5,%6,%7}, {%8,%9}, {%0,%1,%2,%3};\n"
        : "+f"(c[0]), "+f"(c[1]), "+f"(c[2]), "+f"(c[3])
        : "r"(a[0]), "r"(a[1]), "r"(a[2]), "r"(a[3]), "r"(b0), "r"(b1));
}

#define LDP 40            /* padded row: 32 data + 8 pad bf16 */
#define TILEB (128*LDP)   /* elements per buffer */
#define NKT 36            /* 1152/32 */

__global__ __launch_bounds__(256) void gemm_bf16_kernel() {
    const int N = 2*DIx;
    __shared__ __align__(16) __nv_bfloat16 As[2][TILEB];
    __shared__ __align__(16) __nv_bfloat16 Bs[2][TILEB];
    int tid = threadIdx.x;
    int lane = tid & 31, warp = tid >> 5;
    int warpM = warp >> 1, warpN = warp & 1;
    int bn = blockIdx.x, bm = blockIdx.y;
    int g = lane >> 2, t = lane & 3;

    int lr = tid >> 2;       /* 0..63 loader row */
    int lc = tid & 3;        /* 16B chunk */
    const __nv_bfloat16* Asrc0 = g_Abf + (size_t)(bm*128 + lr)*KEXP + lc*8;
    const __nv_bfloat16* Asrc1 = Asrc0 + (size_t)64*KEXP;
    const __nv_bfloat16* Bsrc0 = g_Bt  + (size_t)(bn*128 + lr)*KEXP + lc*8;
    const __nv_bfloat16* Bsrc1 = Bsrc0 + (size_t)64*KEXP;
    uint32_t a_d0 = (uint32_t)__cvta_generic_to_shared(&As[0][lr*LDP + lc*8]);
    uint32_t a_d1 = (uint32_t)__cvta_generic_to_shared(&As[0][(64+lr)*LDP + lc*8]);
    uint32_t b_d0 = (uint32_t)__cvta_generic_to_shared(&Bs[0][lr*LDP + lc*8]);
    uint32_t b_d1 = (uint32_t)__cvta_generic_to_shared(&Bs[0][(64+lr)*LDP + lc*8]);
    const uint32_t BUFB = TILEB*2;  /* bytes per buffer */

    float acc[2][8][4];
    #pragma unroll
    for (int i = 0; i < 2; i++)
        #pragma unroll
        for (int j = 0; j < 8; j++)
            #pragma unroll
            for (int q = 0; q < 4; q++) acc[i][j][q] = 0.f;

    cp16(a_d0, Asrc0); cp16(a_d1, Asrc1);
    cp16(b_d0, Bsrc0); cp16(b_d1, Bsrc1);
    cp_commit();

    for (int kt = 0; kt < NKT; kt++) {
        int buf = kt & 1;
        if (kt + 1 < NKT) {
            uint32_t off = (buf ^ 1) * BUFB;
            cp16(a_d0 + off, Asrc0 + (kt+1)*32);
            cp16(a_d1 + off, Asrc1 + (kt+1)*32);
            cp16(b_d0 + off, Bsrc0 + (kt+1)*32);
            cp16(b_d1 + off, Bsrc1 + (kt+1)*32);
            cp_commit();
            cp_wait<1>();
        } else {
            cp_commit();
            cp_wait<0>();
        }
        __syncthreads();
        const __nv_bfloat16* A_s = As[buf];
        const __nv_bfloat16* B_s = Bs[buf];
        #pragma unroll
        for (int ks = 0; ks < 2; ks++) {
            int kk = ks*16 + t*2;
            uint32_t af[2][4];
            #pragma unroll
            for (int i = 0; i < 2; i++) {
                int m0 = warpM*32 + i*16;
                af[i][0] = *(const uint32_t*)&A_s[(m0+g)*LDP   + kk];
                af[i][1] = *(const uint32_t*)&A_s[(m0+g+8)*LDP + kk];
                af[i][2] = *(const uint32_t*)&A_s[(m0+g)*LDP   + kk + 8];
                af[i][3] = *(const uint32_t*)&A_s[(m0+g+8)*LDP + kk + 8];
            }
            #pragma unroll
            for (int j = 0; j < 8; j++) {
                int n = warpN*64 + j*8 + g;
                uint32_t b0 = *(const uint32_t*)&B_s[n*LDP + kk];
                uint32_t b1 = *(const uint32_t*)&B_s[n*LDP + kk + 8];
                mma_bf16(acc[0][j], af[0], b0, b1);
                mma_bf16(acc[1][j], af[1], b0, b1);
            }
        }
        __syncthreads();
    }

    #pragma unroll
    for (int i = 0; i < 2; i++) {
        int r0 = bm*128 + warpM*32 + i*16 + g;
        #pragma unroll
        for (int j = 0; j < 8; j++) {
            int col = bn*128 + warpN*64 + j*8 + t*2;
            *(float2*)(g_xz + (size_t)r0*N + col)     = make_float2(acc[i][j][0], acc[i][j][1]);
            *(float2*)(g_xz + (size_t)(r0+8)*N + col) = make_float2(acc[i][j][2], acc[i][j][3]);
        }
    }
}

/* ------------- 3. causal depthwise conv (K=4) + SiLU, sliding window ------------- */
#define CTC 64
__global__ __launch_bounds__(256) void conv_silu_kernel(const float* __restrict__ cw,
                                                        const float* __restrict__ cb) {
    int d = blockIdx.x*256 + threadIdx.x;   /* 0..767 */
    int tc = blockIdx.y;                     /* 0..63  */
    int b  = blockIdx.z;
    int t0 = tc*CTC;
    const long stride = 2*DIx;
    const float* xp = g_xz + (size_t)(b*Lx + t0)*stride + d;
    float w0 = cw[d*4+0], w1 = cw[d*4+1], w2 = cw[d*4+2], w3 = cw[d*4+3];
    float bias = cb[d];
    float xm1, xm2, xm3;
    if (tc == 0) { xm1 = 0.f; xm2 = 0.f; xm3 = 0.f; }
    else {
        xm1 = xp[-1*stride];
        xm2 = xp[-2*stride];
        xm3 = xp[-3*stride];
    }
    float* yp = g_xc + (size_t)(b*Lx + t0)*DIx + d;
    #pragma unroll 4
    for (int t = 0; t < CTC; t++) {
        float cur = xp[(long)t*stride];
        float acc = bias + w3*cur + w2*xm1 + w1*xm2 + w0*xm3;
        yp[(long)t*DIx] = siluf(acc);
        xm3 = xm2; xm2 = xm1; xm1 = cur;
    }
}

/* ------------- 4. xproj: g_xc[32768,768] @ W_xproj[768,56], 8x7 tile ------------- */
__global__ __launch_bounds__(128) void xproj_kernel(const float* __restrict__ W) {
    __shared__ float As[32][128];
    __shared__ float Ws[32][56];
    int tid = threadIdx.x;
    int m0 = blockIdx.x * 128;
    int rm = (tid >> 3) * 8, cn = (tid & 7) * 7;
    float acc[8][7] = {};
    for (int k0 = 0; k0 < DIx; k0 += 32) {
        #pragma unroll
        for (int l = 0; l < 8; l++) {
            int f = tid + l*128;              /* 0..1023 float4 slots */
            int r = f >> 3, c4 = (f & 7)*4;
            float4 v = *(const float4*)(g_xc + (size_t)(m0+r)*DIx + k0 + c4);
            As[c4+0][r] = v.x; As[c4+1][r] = v.y; As[c4+2][r] = v.z; As[c4+3][r] = v.w;
        }
        #pragma unroll
        for (int l = 0; l < 4; l++) {
            int f = tid + l*128;
            if (f < 448) {
                int kr = f / 14, c4 = (f % 14)*4;
                *(float4*)(&Ws[kr][c4]) = *(const float4*)(W + (size_t)(k0+kr)*56 + c4);
            }
        }
        __syncthreads();
        #pragma unroll
        for (int k = 0; k < 32; k++) {
            float ra[8], rw[7];
            #pragma unroll
            for (int i = 0; i < 8; i++) ra[i] = As[k][rm+i];
            #pragma unroll
            for (int j = 0; j < 7; j++) rw[j] = Ws[k][cn+j];
            #pragma unroll
            for (int i = 0; i < 8; i++)
                #pragma unroll
                for (int j = 0; j < 7; j++) acc[i][j] += ra[i]*rw[j];
        }
        __syncthreads();
    }
    #pragma unroll
    for (int i = 0; i < 8; i++)
        #pragma unroll
        for (int j = 0; j < 7; j++) {
            int cc = cn + j;
            size_t row = (size_t)(m0 + rm + i);
            float v = acc[i][j];
            if (cc < 24)       g_dtr[row*DTRx + cc] = v;
            else if (cc < 40)  g_Bmat[row*Sx + (cc-24)] = v;
            else               g_Cmat[row*Sx + (cc-40)] = v;
        }
}

/* ------------- 5. dt GEMM: g_dtr[32768,24] @ W_dt[24,768] + bias -> softplus ------------- */
__global__ __launch_bounds__(256) void dt_gemm_kernel(const float* __restrict__ Wdt,
                                                      const float* __restrict__ bias) {
    __shared__ float As[64][24];
    __shared__ float Ws[24][128];
    int tid = threadIdx.x;
    int n0 = blockIdx.x * 128, m0 = blockIdx.y * 64;
    #pragma unroll
    for (int l = 0; l < 2; l++) {
        int f = tid + l*256;
        if (f < 384) {
            int r = f / 6, c4 = (f % 6)*4;
            *(float4*)(&As[r][c4]) = *(const float4*)(g_dtr + (size_t)(m0+r)*DTRx + c4);
        }
    }
    #pragma unroll
    for (int l = 0; l < 3; l++) {
        int f = tid + l*256;
        int kr = f >> 5, c4 = (f & 31)*4;
        *(float4*)(&Ws[kr][c4]) = *(const float4*)(Wdt + (size_t)kr*DIx + n0 + c4);
    }
    __syncthreads();
    int rm = (tid >> 5)*8, cn = (tid & 31)*4;
    float acc[8][4] = {};
    #pragma unroll
    for (int k = 0; k < 24; k++) {
        float rw0 = Ws[k][cn], rw1 = Ws[k][cn+1], rw2 = Ws[k][cn+2], rw3 = Ws[k][cn+3];
        #pragma unroll
        for (int i = 0; i < 8; i++) {
            float a = As[rm+i][k];
            acc[i][0] += a*rw0; acc[i][1] += a*rw1; acc[i][2] += a*rw2; acc[i][3] += a*rw3;
        }
    }
    float b0 = bias[n0+cn], b1 = bias[n0+cn+1], b2 = bias[n0+cn+2], b3 = bias[n0+cn+3];
    #pragma unroll
    for (int i = 0; i < 8; i++) {
        float4 o;
        o.x = softplusf(acc[i][0] + b0);
        o.y = softplusf(acc[i][1] + b1);
        o.z = softplusf(acc[i][2] + b2);
        o.w = softplusf(acc[i][3] + b3);
        *(float4*)(g_dt + (size_t)(m0+rm+i)*DIx + n0 + cn) = o;
    }
}

/* ------------- 6. A = -exp(A_log) ------------- */
__global__ void prep_A_kernel(const float* __restrict__ A_log) {
    int i = blockIdx.x*256 + threadIdx.x;
    if (i < DIx*Sx) g_A[i] = -__expf(A_log[i]);
}

/* ------------- 7. scan pass1: per-chunk final state + dt-sum ------------- */
__global__ __launch_bounds__(128) void scan_pass1_kernel() {
    int d = blockIdx.x*128 + threadIdx.x;
    int c = blockIdx.y, b = blockIdx.z;
    float a[Sx], h[Sx];
    const float4* Ap = (const float4*)(g_A + d*Sx);
    #pragma unroll
    for (int q = 0; q < 4; q++) {
        float4 v = Ap[q];
        a[q*4+0] = v.x; a[q*4+1] = v.y; a[q*4+2] = v.z; a[q*4+3] = v.w;
    }
    #pragma unroll
    for (int s = 0; s < Sx; s++) h[s] = 0.f;
    float ds = 0.f;
    int row0 = b*Lx + c*CLEN;
    const float* dtp = g_dt + (size_t)row0*DIx + d;
    const float* xp  = g_xc + (size_t)row0*DIx + d;
    const float4* Bp = (const float4*)(g_Bmat + (size_t)row0*Sx);
    #pragma unroll 2
    for (int t = 0; t < CLEN; t++) {
        float dv = dtp[(size_t)t*DIx];
        float xv = xp[(size_t)t*DIx];
        float4 q0 = Bp[t*4+0], q1 = Bp[t*4+1], q2 = Bp[t*4+2], q3 = Bp[t*4+3];
        float Bv[16] = {q0.x,q0.y,q0.z,q0.w,q1.x,q1.y,q1.z,q1.w,
                        q2.x,q2.y,q2.z,q2.w,q3.x,q3.y,q3.z,q3.w};
        float c1 = dv*xv;
        ds += dv;
        #pragma unroll
        for (int s = 0; s < Sx; s++)
            h[s] = __expf(dv*a[s])*h[s] + c1*Bv[s];
    }
    size_t base = (((size_t)b*NCH + c)*DIx + d)*Sx;
    #pragma unroll
    for (int s = 0; s < Sx; s += 4)
        *(float4*)(g_hfin + base + s) = make_float4(h[s], h[s+1], h[s+2], h[s+3]);
    g_dtsum[(b*NCH + c)*DIx + d] = ds;
}

/* ------------- 8. sequential chunk combine ------------- */
__global__ __launch_bounds__(256) void scan_combine_kernel() {
    int gid = blockIdx.x*256 + threadIdx.x;  /* < 8*768*16 */
    int s = gid & 15;
    int d = (gid >> 4) % DIx;
    int b = gid / (DIx*Sx);
    float a = g_A[d*Sx + s];
    float H = 0.f;
    for (int c = 0; c < NCH; c++) {
        size_t idx = (((size_t)b*NCH + c)*DIx + d)*Sx + s;
        g_Hini[idx] = H;
        float ds = g_dtsum[(b*NCH + c)*DIx + d];
        H = __expf(a*ds)*H + g_hfin[idx];
    }
}

/* ------------- 9. scan pass2 fused: full scan per chunk, accumulate yv partial ------------- */
__global__ __launch_bounds__(128) void scan_pass2_kernel(const float* __restrict__ Dskip) {
    int d = blockIdx.x*128 + threadIdx.x;
    int c = blockIdx.y, b = blockIdx.z;
    float a[Sx], h[Sx];
    const float4* Ap = (const float4*)(g_A + d*Sx);
    #pragma unroll
    for (int q = 0; q < 4; q++) {
        float4 v = Ap[q];
        a[q*4+0] = v.x; a[q*4+1] = v.y; a[q*4+2] = v.z; a[q*4+3] = v.w;
    }
    size_t hbase = (((size_t)b*NCH + c)*DIx + d)*Sx;
    #pragma unroll
    for (int q = 0; q < 4; q++) {
        float4 v = *(const float4*)(g_Hini + hbase + q*4);
        h[q*4+0] = v.x; h[q*4+1] = v.y; h[q*4+2] = v.z; h[q*4+3] = v.w;
    }
    int row0 = b*Lx + c*CLEN;
    const float* dtp = g_dt + (size_t)row0*DIx + d;
    const float* xp  = g_xc + (size_t)row0*DIx + d;
    const float* zp  = g_xz + (size_t)row0*(2*DIx) + DIx + d;
    const float4* Bp = (const float4*)(g_Bmat + (size_t)row0*Sx);
    const float4* Cp = (const float4*)(g_Cmat + (size_t)row0*Sx);
    float Dk = Dskip[d];
    float yv = 0.f;
    #pragma unroll 2
    for (int t = 0; t < CLEN; t++) {
        float dv = dtp[(size_t)t*DIx];
        float xv = xp[(size_t)t*DIx];
        float zv = zp[(size_t)t*(2*DIx)];
        float4 q0 = Bp[t*4+0], q1 = Bp[t*4+1], q2 = Bp[t*4+2], q3 = Bp[t*4+3];
        float Bv[16] = {q0.x,q0.y,q0.z,q0.w,q1.x,q1.y,q1.z,q1.w,
                        q2.x,q2.y,q2.z,q2.w,q3.x,q3.y,q3.z,q3.w};
        float4 r0 = Cp[t*4+0], r1 = Cp[t*4+1], r2 = Cp[t*4+2], r3 = Cp[t*4+3];
        float Cv[16] = {r0.x,r0.y,r0.z,r0.w,r1.x,r1.y,r1.z,r1.w,
                        r2.x,r2.y,r2.z,r2.w,r3.x,r3.y,r3.z,r3.w};
        float c1 = dv*xv;
        float y = 0.f;
        #pragma unroll
        for (int s = 0; s < Sx; s++) {
            h[s] = __expf(dv*a[s])*h[s] + c1*Bv[s];
            y += h[s]*Cv[s];
        }
        yv += (y + xv*Dk) * siluf(zv);
    }
    g_yvpart[(b*NCH + c)*DIx + d] = yv;
}

/* ------------- 10. mean over L of x (partials, deterministic) ------------- */
__global__ __launch_bounds__(384) void meanx_part_kernel(const float* __restrict__ x) {
    int b = blockIdx.x, cz = blockIdx.y, j = threadIdx.x;
    float acc = 0.f;
    for (int i = 0; i < 256; i++)
        acc += x[((size_t)b*Lx + cz*256 + i)*Dx + j];
    g_xpart[(b*16 + cz)*Dx + j] = acc;
}

/* ------------- 12. pooled = (sum_x + sum_yv @ W_out)/L ------------- */
__global__ __launch_bounds__(256) void pooled_gemm_kernel(const float* __restrict__ Wout) {
    __shared__ float myv[DIx];
    __shared__ float red[8][32];
    int tid = threadIdx.x;
    int b = blockIdx.x, j0 = blockIdx.y*32;
    for (int f = tid; f < DIx; f += 256) {
        float s = 0.f;
        #pragma unroll 4
        for (int cc = 0; cc < NCH; cc++) s += g_yvpart[(b*NCH + cc)*DIx + f];
        myv[f] = s;
    }
    __syncthreads();
    int j = j0 + (tid & 31), seg = tid >> 5;
    float acc = 0.f;
    for (int d = seg*96; d < seg*96 + 96; d++)
        acc += myv[d] * Wout[(size_t)d*Dx + j];
    red[seg][tid & 31] = acc;
    __syncthreads();
    if (seg == 0) {
        float tot = 0.f;
        #pragma unroll
        for (int s = 0; s < 8; s++) tot += red[s][tid];
        float mx = 0.f;
        #pragma unroll
        for (int cz = 0; cz < 16; cz++) mx += g_xpart[(b*16 + cz)*Dx + j];
        g_pooled[b*Dx + j] = (mx + tot) * (1.f/Lx);
    }
}

/* ------------- 13. fc: pooled[8,384] @ W_fc[384,256] + b_fc ------------- */
__global__ __launch_bounds__(256) void fc_kernel(const float* __restrict__ Wfc,
                                                 const float* __restrict__ bfc) {
    __shared__ float ps[Dx];
    int b = blockIdx.x, tid = threadIdx.x;
    for (int f = tid; f < Dx; f += 256) ps[f] = g_pooled[b*Dx + f];
    __syncthreads();
    float acc = bfc[tid];
    for (int jj = 0; jj < Dx; jj++) acc += ps[jj] * Wfc[(size_t)jj*256 + tid];
    g_hfc[b*256 + tid] = acc;
}

/* ------------- 14. head: batchnorm(8) + relu + cls ------------- */
__global__ __launch_bounds__(256) void head_kernel(const float* __restrict__ gamma,
                                                   const float* __restrict__ beta,
                                                   const float* __restrict__ Wcls,
                                                   const float* __restrict__ bcls,
                                                   float* __restrict__ out) {
    __shared__ float hs[Bx*256];
    int tid = threadIdx.x;
    for (int f = tid; f < Bx*256; f += 256) hs[f] = g_hfc[f];
    __syncthreads();
    int c = tid;
    float mu = 0.f;
    #pragma unroll
    for (int b = 0; b < Bx; b++) mu += hs[b*256 + c];
    mu *= 0.125f;
    float var = 0.f;
    #pragma unroll
    for (int b = 0; b < Bx; b++) { float dd = hs[b*256 + c] - mu; var += dd*dd; }
    var *= 0.125f;
    float inv = rsqrtf(var + 1e-5f);
    float ga = gamma[c], be = beta[c];
    #pragma unroll
    for (int b = 0; b < Bx; b++) {
        float v = (hs[b*256 + c] - mu)*inv*ga + be;
        hs[b*256 + c] = fmaxf(v, 0.f);
    }
    __syncthreads();
    for (int t = tid; t < Bx*40; t += 256) {
        int b = t / 40, n = t % 40;
        float acc = bcls[n];
        for (int c2 = 0; c2 < 256; c2++) acc += hs[b*256 + c2] * Wcls[c2*40 + n];
        out[t] = acc;
    }
}

/* ------------- launch ------------- */
extern "C" void kernel_launch(void* const* d_in, const int* in_sizes, int n_in,
                              void* d_out, int out_size) {
    const float* x       = (const float*)d_in[0];
    const float* ln_w    = (const float*)d_in[1];
    const float* W_in    = (const float*)d_in[2];
    const float* conv_w  = (const float*)d_in[3];
    const float* conv_b  = (const float*)d_in[4];
    const float* W_xproj = (const float*)d_in[5];
    const float* W_dt    = (const float*)d_in[6];
    const float* dt_bias = (const float*)d_in[7];
    const float* A_log   = (const float*)d_in[8];
    const float* Dskip   = (const float*)d_in[9];
    const float* W_out   = (const float*)d_in[10];
    const float* W_fc    = (const float*)d_in[11];
    const float* b_fc    = (const float*)d_in[12];
    const float* bn_g    = (const float*)d_in[13];
    const float* bn_b    = (const float*)d_in[14];
    const float* W_cls   = (const float*)d_in[15];
    const float* b_cls   = (const float*)d_in[16];
    float* out = (float*)d_out;

    rmsnorm_kernel<<<Rx, 128>>>(x, ln_w);
    prepB_kernel<<<Dx, 256>>>(W_in);
    gemm_bf16_kernel<<<dim3(12, Rx/128), 256>>>();
    conv_silu_kernel<<<dim3(3, Lx/CTC, Bx), 256>>>(conv_w, conv_b);
    xproj_kernel<<<Rx/128, 128>>>(W_xproj);
    dt_gemm_kernel<<<dim3(6, Rx/64), 256>>>(W_dt, dt_bias);
    prep_A_kernel<<<48, 256>>>(A_log);
    scan_pass1_kernel<<<dim3(6, NCH, Bx), 128>>>();
    scan_combine_kernel<<<(Bx*DIx*Sx)/256, 256>>>();
    scan_pass2_kernel<<<dim3(6, NCH, Bx), 128>>>(Dskip);
    meanx_part_kernel<<<dim3(Bx, 16), 384>>>(x);
    pooled_gemm_kernel<<<dim3(Bx, 12), 256>>>(W_out);
    fc_kernel<<<Bx, 256>>>(W_fc, b_fc);
    head_kernel<<<1, 256>>>(bn_g, bn_b, W_cls, b_cls, out);
}

// round 9
// speedup vs baseline: 2.0834x; 1.0412x over previous
#include <cuda_runtime.h>
#include <cuda_bf16.h>
#include <math.h>
#include <stdint.h>

#define Bx   8
#define Lx   4096
#define Dx   384
#define DIx  768
#define Sx   16
#define DTRx 24
#define Rx   (Bx*Lx)        /* 32768 rows */
#define NCH  32
#define CLEN (Lx/NCH)       /* 128 */
#define KEXP 1152           /* 3*Dx expanded K */

/* ------------- device scratch (static, no allocations) ------------- */
__device__ __align__(128) __nv_bfloat16 g_Abf[(size_t)Rx*KEXP];
__device__ __align__(128) __nv_bfloat16 g_Bt [(size_t)2*DIx*KEXP];
__device__ __align__(128) float g_xz [(size_t)Rx*2*DIx];
__device__ __align__(128) float g_xc [(size_t)Rx*DIx];
__device__ __align__(128) float g_dtr[(size_t)Rx*DTRx];
__device__ __align__(128) float g_Bmat[(size_t)Rx*Sx];
__device__ __align__(128) float g_Cmat[(size_t)Rx*Sx];
__device__ __align__(128) float g_dt [(size_t)Rx*DIx];
__device__ __align__(128) float g_A  [DIx*Sx];
__device__ __align__(128) float g_hfin[(size_t)Bx*NCH*DIx*Sx];
__device__ __align__(128) float g_Hini[(size_t)Bx*NCH*DIx*Sx];
__device__ __align__(128) float g_dtsum[Bx*NCH*DIx];
__device__ __align__(128) float g_yvpart[Bx*NCH*DIx];
__device__ __align__(128) float g_xpart[Bx*16*Dx];
__device__ __align__(128) float g_pooled[Bx*Dx];
__device__ __align__(128) float g_hfc[Bx*256];

__device__ __forceinline__ float softplusf(float v) {
    return v > 20.f ? v : log1pf(__expf(v));
}
__device__ __forceinline__ float siluf(float v) {
    return v / (1.f + __expf(-v));
}

/* ------------- 1. RMSNorm -> split-bf16 A' = [hi | lo | hi] ------------- */
__global__ __launch_bounds__(128) void rmsnorm_kernel(const float* __restrict__ x,
                                                      const float* __restrict__ w) {
    int row = blockIdx.x, tid = threadIdx.x;
    const float* xr = x + (size_t)row*Dx;
    float v0 = xr[tid], v1 = xr[tid+128], v2 = xr[tid+256];
    float ss = v0*v0 + v1*v1 + v2*v2;
    #pragma unroll
    for (int o = 16; o; o >>= 1) ss += __shfl_xor_sync(0xffffffffu, ss, o);
    __shared__ float sm[4];
    if ((tid & 31) == 0) sm[tid >> 5] = ss;
    __syncthreads();
    float tot = sm[0] + sm[1] + sm[2] + sm[3];
    float sc  = rsqrtf(tot * (1.f/Dx) + 1e-5f);
    __nv_bfloat16* o = g_Abf + (size_t)row*KEXP;
    float ys[3] = { v0*sc*w[tid], v1*sc*w[tid+128], v2*sc*w[tid+256] };
    int cs[3] = { tid, tid+128, tid+256 };
    #pragma unroll
    for (int q = 0; q < 3; q++) {
        __nv_bfloat16 h = __float2bfloat16(ys[q]);
        __nv_bfloat16 l = __float2bfloat16(ys[q] - __bfloat162float(h));
        o[cs[q]]       = h;
        o[384 + cs[q]] = l;
        o[768 + cs[q]] = h;
    }
}

/* ------------- 1b. build B'^T [1536][1152] = [hi | hi | lo] of W_in^T ------------- */
__global__ __launch_bounds__(256) void prepB_kernel(const float* __restrict__ W) {
    int k = blockIdx.x;  /* 0..383 */
    for (int n = threadIdx.x; n < 2*DIx; n += 256) {
        float v = W[(size_t)k*(2*DIx) + n];
        __nv_bfloat16 h = __float2bfloat16(v);
        __nv_bfloat16 l = __float2bfloat16(v - __bfloat162float(h));
        g_Bt[(size_t)n*KEXP + k]       = h;
        g_Bt[(size_t)n*KEXP + 384 + k] = h;
        g_Bt[(size_t)n*KEXP + 768 + k] = l;
    }
}

/* ------------- 2. GEMM1 bf16 TC (ldmatrix, 2-stage), fused conv epilogue ------------- */
__device__ __forceinline__ void cp16(uint32_t dst, const void* src) {
    asm volatile("cp.async.cg.shared.global [%0], [%1], 16;\n" :: "r"(dst), "l"(src));
}
__device__ __forceinline__ void cp_commit() {
    asm volatile("cp.async.commit_group;\n");
}
template<int N> __device__ __forceinline__ void cp_wait() {
    asm volatile("cp.async.wait_group %0;\n" :: "n"(N));
}
__device__ __forceinline__ void mma_bf16(float* c, const uint32_t* a, uint32_t b0, uint32_t b1) {
    asm volatile("mma.sync.aligned.m16n8k16.row.col.f32.bf16.bf16.f32 "
        "{%0,%1,%2,%3}, {%4,%5,%6,%7}, {%8,%9}, {%0,%1,%2,%3};\n"
        : "+f"(c[0]), "+f"(c[1]), "+f"(c[2]), "+f"(c[3])
        : "r"(a[0]), "r"(a[1]), "r"(a[2]), "r"(a[3]), "r"(b0), "r"(b1));
}
__device__ __forceinline__ void ldsm_x4(uint32_t* r, uint32_t addr) {
    asm volatile("ldmatrix.sync.aligned.m8n8.x4.shared.b16 {%0,%1,%2,%3}, [%4];"
        : "=r"(r[0]), "=r"(r[1]), "=r"(r[2]), "=r"(r[3]) : "r"(addr));
}

#define LDP 40            /* padded row: 32 data + 8 pad bf16 */
#define TILEB (128*LDP)   /* elements per buffer */
#define NKT 36            /* 1152/32 */
#define CROW 132          /* conv stage row stride (floats) */

__global__ __launch_bounds__(256) void gemm_bf16_kernel(const float* __restrict__ cw,
                                                        const float* __restrict__ cb) {
    const int N = 2*DIx;
    __shared__ __align__(16) __nv_bfloat16 As[2][TILEB];
    __shared__ __align__(16) __nv_bfloat16 Bs[2][TILEB];
    int tid = threadIdx.x;
    int lane = tid & 31, warp = tid >> 5;
    int warpM = warp >> 1, warpN = warp & 1;
    int bn = blockIdx.x, bm = blockIdx.y;
    int g = lane >> 2, t = lane & 3;

    int lr = tid >> 2, lc = tid & 3;
    const __nv_bfloat16* Asrc0 = g_Abf + (size_t)(bm*128 + lr)*KEXP + lc*8;
    const __nv_bfloat16* Asrc1 = Asrc0 + (size_t)64*KEXP;
    const __nv_bfloat16* Bsrc0 = g_Bt  + (size_t)(bn*128 + lr)*KEXP + lc*8;
    const __nv_bfloat16* Bsrc1 = Bsrc0 + (size_t)64*KEXP;
    uint32_t a_d0 = (uint32_t)__cvta_generic_to_shared(&As[0][lr*LDP + lc*8]);
    uint32_t a_d1 = (uint32_t)__cvta_generic_to_shared(&As[0][(64+lr)*LDP + lc*8]);
    uint32_t b_d0 = (uint32_t)__cvta_generic_to_shared(&Bs[0][lr*LDP + lc*8]);
    uint32_t b_d1 = (uint32_t)__cvta_generic_to_shared(&Bs[0][(64+lr)*LDP + lc*8]);
    const uint32_t BUFB = TILEB*2;

    uint32_t as_base = (uint32_t)__cvta_generic_to_shared(&As[0][0]);
    uint32_t bs_base = (uint32_t)__cvta_generic_to_shared(&Bs[0][0]);
    /* ldmatrix per-lane address components (bytes) */
    uint32_t a_lane = ((uint32_t)(lane & 15)*LDP + (lane >> 4)*8) * 2;
    uint32_t b_lane = (((uint32_t)((lane & 7) + ((lane >> 4) << 3)))*LDP
                       + (((lane >> 3) & 1) << 3)) * 2;

    float acc[2][8][4];
    #pragma unroll
    for (int i = 0; i < 2; i++)
        #pragma unroll
        for (int j = 0; j < 8; j++)
            #pragma unroll
            for (int q = 0; q < 4; q++) acc[i][j][q] = 0.f;

    cp16(a_d0, Asrc0); cp16(a_d1, Asrc1);
    cp16(b_d0, Bsrc0); cp16(b_d1, Bsrc1);
    cp_commit();

    for (int kt = 0; kt < NKT; kt++) {
        int buf = kt & 1;
        if (kt + 1 < NKT) {
            uint32_t off = (buf ^ 1) * BUFB;
            cp16(a_d0 + off, Asrc0 + (kt+1)*32);
            cp16(a_d1 + off, Asrc1 + (kt+1)*32);
            cp16(b_d0 + off, Bsrc0 + (kt+1)*32);
            cp16(b_d1 + off, Bsrc1 + (kt+1)*32);
            cp_commit();
            cp_wait<1>();
        } else {
            cp_commit();
            cp_wait<0>();
        }
        __syncthreads();
        uint32_t ab = as_base + buf*BUFB;
        uint32_t bb = bs_base + buf*BUFB;
        #pragma unroll
        for (int ks = 0; ks < 2; ks++) {
            int kk = ks*16;
            uint32_t af[2][4], bfr[4][4];
            ldsm_x4(af[0], ab + a_lane + ((warpM*32 +  0)*LDP + kk)*2);
            ldsm_x4(af[1], ab + a_lane + ((warpM*32 + 16)*LDP + kk)*2);
            #pragma unroll
            for (int jj = 0; jj < 4; jj++)
                ldsm_x4(bfr[jj], bb + b_lane + ((warpN*64 + jj*16)*LDP + kk)*2);
            #pragma unroll
            for (int jj = 0; jj < 4; jj++) {
                mma_bf16(acc[0][jj*2+0], af[0], bfr[jj][0], bfr[jj][1]);
                mma_bf16(acc[1][jj*2+0], af[1], bfr[jj][0], bfr[jj][1]);
                mma_bf16(acc[0][jj*2+1], af[0], bfr[jj][2], bfr[jj][3]);
                mma_bf16(acc[1][jj*2+1], af[1], bfr[jj][2], bfr[jj][3]);
            }
        }
        __syncthreads();
    }

    /* write xz */
    #pragma unroll
    for (int i = 0; i < 2; i++) {
        int r0 = bm*128 + warpM*32 + i*16 + g;
        #pragma unroll
        for (int j = 0; j < 8; j++) {
            int col = bn*128 + warpN*64 + j*8 + t*2;
            *(float2*)(g_xz + (size_t)r0*N + col)     = make_float2(acc[i][j][0], acc[i][j][1]);
            *(float2*)(g_xz + (size_t)(r0+8)*N + col) = make_float2(acc[i][j][2], acc[i][j][3]);
        }
    }

    /* fused causal depthwise conv + SiLU for the xp half (bn<6).
       Tile rows = 128 consecutive timesteps of one batch. 4 chunks of 32 rows;
       3-row halo passed from the previous warpM's registers. Tile rows 0..2
       are finished by conv_fix_kernel. */
    if (bn < 6) {
        float* cbuf = (float*)&As[0][0];   /* 35 x CROW floats = 18480 B */
        int col = tid & 127;
        int d = bn*128 + col;
        float w0 = cw[d*4+0], w1 = cw[d*4+1], w2 = cw[d*4+2], w3 = cw[d*4+3];
        float bias = cb[d];
        int rbase = tid >> 7;              /* 0 or 1 */
        for (int cc = 0; cc < 4; cc++) {
            __syncthreads();
            if (warpM == cc) {
                #pragma unroll
                for (int i = 0; i < 2; i++)
                    #pragma unroll
                    for (int j = 0; j < 8; j++)
                        #pragma unroll
                        for (int q = 0; q < 4; q++) {
                            int rl = i*16 + g + ((q >> 1) ? 8 : 0) + 3;
                            int c2 = warpN*64 + j*8 + t*2 + (q & 1);
                            cbuf[rl*CROW + c2] = acc[i][j][q];
                        }
            }
            if (cc > 0 && warpM == cc-1 && g >= 5) {
                #pragma unroll
                for (int j = 0; j < 8; j++)
                    #pragma unroll
                    for (int q = 2; q < 4; q++) {
                        int c2 = warpN*64 + j*8 + t*2 + (q & 1);
                        cbuf[(g-5)*CROW + c2] = acc[1][j][q];
                    }
            }
            __syncthreads();
            #pragma unroll
            for (int k = 0; k < 16; k++) {
                int row = rbase + 2*k;
                if (cc == 0 && row < 3) continue;
                float x0 = cbuf[row*CROW + col];
                float x1 = cbuf[(row+1)*CROW + col];
                float x2 = cbuf[(row+2)*CROW + col];
                float x3 = cbuf[(row+3)*CROW + col];
                float v = bias + w3*x3 + w2*x2 + w1*x1 + w0*x0;
                size_t gr = (size_t)bm*128 + cc*32 + row;
                g_xc[gr*DIx + d] = siluf(v);
            }
        }
    }
}

/* ------------- 2b. conv fixup: first 3 rows of each 128-row tile ------------- */
__global__ __launch_bounds__(256) void conv_fix_kernel(const float* __restrict__ cw,
                                                       const float* __restrict__ cb) {
    int idx = blockIdx.x*256 + threadIdx.x;
    if (idx >= 256*3*DIx) return;
    int d = idx % DIx;
    int rr = (idx / DIx) % 3;
    int tile = idx / (3*DIx);
    size_t gr = (size_t)tile*128 + rr;
    int t = (int)(gr % Lx);
    const float* xp = g_xz + gr*(2*DIx) + d;
    float acc = cb[d] + cw[d*4+3]*xp[0];
    if (t >= 1) acc += cw[d*4+2]*xp[-(long)(2*DIx)];
    if (t >= 2) acc += cw[d*4+1]*xp[-(long)2*(2*DIx)];
    if (t >= 3) acc += cw[d*4+0]*xp[-(long)3*(2*DIx)];
    g_xc[gr*DIx + d] = siluf(acc);
}

/* ------------- 4. xproj: g_xc[32768,768] @ W_xproj[768,56], 8x7 tile ------------- */
__global__ __launch_bounds__(128) void xproj_kernel(const float* __restrict__ W) {
    __shared__ float As[32][128];
    __shared__ float Ws[32][56];
    int tid = threadIdx.x;
    int m0 = blockIdx.x * 128;
    int rm = (tid >> 3) * 8, cn = (tid & 7) * 7;
    float acc[8][7] = {};
    for (int k0 = 0; k0 < DIx; k0 += 32) {
        #pragma unroll
        for (int l = 0; l < 8; l++) {
            int f = tid + l*128;
            int r = f >> 3, c4 = (f & 7)*4;
            float4 v = *(const float4*)(g_xc + (size_t)(m0+r)*DIx + k0 + c4);
            As[c4+0][r] = v.x; As[c4+1][r] = v.y; As[c4+2][r] = v.z; As[c4+3][r] = v.w;
        }
        #pragma unroll
        for (int l = 0; l < 4; l++) {
            int f = tid + l*128;
            if (f < 448) {
                int kr = f / 14, c4 = (f % 14)*4;
                *(float4*)(&Ws[kr][c4]) = *(const float4*)(W + (size_t)(k0+kr)*56 + c4);
            }
        }
        __syncthreads();
        #pragma unroll
        for (int k = 0; k < 32; k++) {
            float ra[8], rw[7];
            #pragma unroll
            for (int i = 0; i < 8; i++) ra[i] = As[k][rm+i];
            #pragma unroll
            for (int j = 0; j < 7; j++) rw[j] = Ws[k][cn+j];
            #pragma unroll
            for (int i = 0; i < 8; i++)
                #pragma unroll
                for (int j = 0; j < 7; j++) acc[i][j] += ra[i]*rw[j];
        }
        __syncthreads();
    }
    #pragma unroll
    for (int i = 0; i < 8; i++)
        #pragma unroll
        for (int j = 0; j < 7; j++) {
            int cc = cn + j;
            size_t row = (size_t)(m0 + rm + i);
            float v = acc[i][j];
            if (cc < 24)       g_dtr[row*DTRx + cc] = v;
            else if (cc < 40)  g_Bmat[row*Sx + (cc-24)] = v;
            else               g_Cmat[row*Sx + (cc-40)] = v;
        }
}

/* ------------- 5. dt GEMM: g_dtr[32768,24] @ W_dt[24,768] + bias -> softplus ------------- */
__global__ __launch_bounds__(256) void dt_gemm_kernel(const float* __restrict__ Wdt,
                                                      const float* __restrict__ bias) {
    __shared__ float As[64][24];
    __shared__ float Ws[24][128];
    int tid = threadIdx.x;
    int n0 = blockIdx.x * 128, m0 = blockIdx.y * 64;
    #pragma unroll
    for (int l = 0; l < 2; l++) {
        int f = tid + l*256;
        if (f < 384) {
            int r = f / 6, c4 = (f % 6)*4;
            *(float4*)(&As[r][c4]) = *(const float4*)(g_dtr + (size_t)(m0+r)*DTRx + c4);
        }
    }
    #pragma unroll
    for (int l = 0; l < 3; l++) {
        int f = tid + l*256;
        int kr = f >> 5, c4 = (f & 31)*4;
        *(float4*)(&Ws[kr][c4]) = *(const float4*)(Wdt + (size_t)kr*DIx + n0 + c4);
    }
    __syncthreads();
    int rm = (tid >> 5)*8, cn = (tid & 31)*4;
    float acc[8][4] = {};
    #pragma unroll
    for (int k = 0; k < 24; k++) {
        float rw0 = Ws[k][cn], rw1 = Ws[k][cn+1], rw2 = Ws[k][cn+2], rw3 = Ws[k][cn+3];
        #pragma unroll
        for (int i = 0; i < 8; i++) {
            float a = As[rm+i][k];
            acc[i][0] += a*rw0; acc[i][1] += a*rw1; acc[i][2] += a*rw2; acc[i][3] += a*rw3;
        }
    }
    float b0 = bias[n0+cn], b1 = bias[n0+cn+1], b2 = bias[n0+cn+2], b3 = bias[n0+cn+3];
    #pragma unroll
    for (int i = 0; i < 8; i++) {
        float4 o;
        o.x = softplusf(acc[i][0] + b0);
        o.y = softplusf(acc[i][1] + b1);
        o.z = softplusf(acc[i][2] + b2);
        o.w = softplusf(acc[i][3] + b3);
        *(float4*)(g_dt + (size_t)(m0+rm+i)*DIx + n0 + cn) = o;
    }
}

/* ------------- 6. A = -exp(A_log) ------------- */
__global__ void prep_A_kernel(const float* __restrict__ A_log) {
    int i = blockIdx.x*256 + threadIdx.x;
    if (i < DIx*Sx) g_A[i] = -__expf(A_log[i]);
}

/* ------------- 7. scan pass1: per-chunk final state + dt-sum ------------- */
__global__ __launch_bounds__(128) void scan_pass1_kernel() {
    int d = blockIdx.x*128 + threadIdx.x;
    int c = blockIdx.y, b = blockIdx.z;
    float a[Sx], h[Sx];
    const float4* Ap = (const float4*)(g_A + d*Sx);
    #pragma unroll
    for (int q = 0; q < 4; q++) {
        float4 v = Ap[q];
        a[q*4+0] = v.x; a[q*4+1] = v.y; a[q*4+2] = v.z; a[q*4+3] = v.w;
    }
    #pragma unroll
    for (int s = 0; s < Sx; s++) h[s] = 0.f;
    float ds = 0.f;
    int row0 = b*Lx + c*CLEN;
    const float* dtp = g_dt + (size_t)row0*DIx + d;
    const float* xp  = g_xc + (size_t)row0*DIx + d;
    const float4* Bp = (const float4*)(g_Bmat + (size_t)row0*Sx);
    #pragma unroll 2
    for (int t = 0; t < CLEN; t++) {
        float dv = dtp[(size_t)t*DIx];
        float xv = xp[(size_t)t*DIx];
        float4 q0 = Bp[t*4+0], q1 = Bp[t*4+1], q2 = Bp[t*4+2], q3 = Bp[t*4+3];
        float Bv[16] = {q0.x,q0.y,q0.z,q0.w,q1.x,q1.y,q1.z,q1.w,
                        q2.x,q2.y,q2.z,q2.w,q3.x,q3.y,q3.z,q3.w};
        float c1 = dv*xv;
        ds += dv;
        #pragma unroll
        for (int s = 0; s < Sx; s++)
            h[s] = __expf(dv*a[s])*h[s] + c1*Bv[s];
    }
    size_t base = (((size_t)b*NCH + c)*DIx + d)*Sx;
    #pragma unroll
    for (int s = 0; s < Sx; s += 4)
        *(float4*)(g_hfin + base + s) = make_float4(h[s], h[s+1], h[s+2], h[s+3]);
    g_dtsum[(b*NCH + c)*DIx + d] = ds;
}

/* ------------- 8. sequential chunk combine ------------- */
__global__ __launch_bounds__(256) void scan_combine_kernel() {
    int gid = blockIdx.x*256 + threadIdx.x;  /* < 8*768*16 */
    int s = gid & 15;
    int d = (gid >> 4) % DIx;
    int b = gid / (DIx*Sx);
    float a = g_A[d*Sx + s];
    float H = 0.f;
    for (int c = 0; c < NCH; c++) {
        size_t idx = (((size_t)b*NCH + c)*DIx + d)*Sx + s;
        g_Hini[idx] = H;
        float ds = g_dtsum[(b*NCH + c)*DIx + d];
        H = __expf(a*ds)*H + g_hfin[idx];
    }
}

/* ------------- 9. scan pass2 fused: full scan per chunk, accumulate yv partial ------------- */
__global__ __launch_bounds__(128) void scan_pass2_kernel(const float* __restrict__ Dskip) {
    int d = blockIdx.x*128 + threadIdx.x;
    int c = blockIdx.y, b = blockIdx.z;
    float a[Sx], h[Sx];
    const float4* Ap = (const float4*)(g_A + d*Sx);
    #pragma unroll
    for (int q = 0; q < 4; q++) {
        float4 v = Ap[q];
        a[q*4+0] = v.x; a[q*4+1] = v.y; a[q*4+2] = v.z; a[q*4+3] = v.w;
    }
    size_t hbase = (((size_t)b*NCH + c)*DIx + d)*Sx;
    #pragma unroll
    for (int q = 0; q < 4; q++) {
        float4 v = *(const float4*)(g_Hini + hbase + q*4);
        h[q*4+0] = v.x; h[q*4+1] = v.y; h[q*4+2] = v.z; h[q*4+3] = v.w;
    }
    int row0 = b*Lx + c*CLEN;
    const float* dtp = g_dt + (size_t)row0*DIx + d;
    const float* xp  = g_xc + (size_t)row0*DIx + d;
    const float* zp  = g_xz + (size_t)row0*(2*DIx) + DIx + d;
    const float4* Bp = (const float4*)(g_Bmat + (size_t)row0*Sx);
    const float4* Cp = (const float4*)(g_Cmat + (size_t)row0*Sx);
    float Dk = Dskip[d];
    float yv = 0.f;
    #pragma unroll 2
    for (int t = 0; t < CLEN; t++) {
        float dv = dtp[(size_t)t*DIx];
        float xv = xp[(size_t)t*DIx];
        float zv = zp[(size_t)t*(2*DIx)];
        float4 q0 = Bp[t*4+0], q1 = Bp[t*4+1], q2 = Bp[t*4+2], q3 = Bp[t*4+3];
        float Bv[16] = {q0.x,q0.y,q0.z,q0.w,q1.x,q1.y,q1.z,q1.w,
                        q2.x,q2.y,q2.z,q2.w,q3.x,q3.y,q3.z,q3.w};
        float4 r0 = Cp[t*4+0], r1 = Cp[t*4+1], r2 = Cp[t*4+2], r3 = Cp[t*4+3];
        float Cv[16] = {r0.x,r0.y,r0.z,r0.w,r1.x,r1.y,r1.z,r1.w,
                        r2.x,r2.y,r2.z,r2.w,r3.x,r3.y,r3.z,r3.w};
        float c1 = dv*xv;
        float y = 0.f;
        #pragma unroll
        for (int s = 0; s < Sx; s++) {
            h[s] = __expf(dv*a[s])*h[s] + c1*Bv[s];
            y += h[s]*Cv[s];
        }
        yv += (y + xv*Dk) * siluf(zv);
    }
    g_yvpart[(b*NCH + c)*DIx + d] = yv;
}

/* ------------- 10. mean over L of x (partials, deterministic) ------------- */
__global__ __launch_bounds__(384) void meanx_part_kernel(const float* __restrict__ x) {
    int b = blockIdx.x, cz = blockIdx.y, j = threadIdx.x;
    float acc = 0.f;
    for (int i = 0; i < 256; i++)
        acc += x[((size_t)b*Lx + cz*256 + i)*Dx + j];
    g_xpart[(b*16 + cz)*Dx + j] = acc;
}

/* ------------- 12. pooled = (sum_x + sum_yv @ W_out)/L ------------- */
__global__ __launch_bounds__(256) void pooled_gemm_kernel(const float* __restrict__ Wout) {
    __shared__ float myv[DIx];
    __shared__ float red[8][32];
    int tid = threadIdx.x;
    int b = blockIdx.x, j0 = blockIdx.y*32;
    for (int f = tid; f < DIx; f += 256) {
        float s = 0.f;
        #pragma unroll 4
        for (int cc = 0; cc < NCH; cc++) s += g_yvpart[(b*NCH + cc)*DIx + f];
        myv[f] = s;
    }
    __syncthreads();
    int j = j0 + (tid & 31), seg = tid >> 5;
    float acc = 0.f;
    for (int d = seg*96; d < seg*96 + 96; d++)
        acc += myv[d] * Wout[(size_t)d*Dx + j];
    red[seg][tid & 31] = acc;
    __syncthreads();
    if (seg == 0) {
        float tot = 0.f;
        #pragma unroll
        for (int s = 0; s < 8; s++) tot += red[s][tid];
        float mx = 0.f;
        #pragma unroll
        for (int cz = 0; cz < 16; cz++) mx += g_xpart[(b*16 + cz)*Dx + j];
        g_pooled[b*Dx + j] = (mx + tot) * (1.f/Lx);
    }
}

/* ------------- 13. fc: pooled[8,384] @ W_fc[384,256] + b_fc ------------- */
__global__ __launch_bounds__(256) void fc_kernel(const float* __restrict__ Wfc,
                                                 const float* __restrict__ bfc) {
    __shared__ float ps[Dx];
    int b = blockIdx.x, tid = threadIdx.x;
    for (int f = tid; f < Dx; f += 256) ps[f] = g_pooled[b*Dx + f];
    __syncthreads();
    float acc = bfc[tid];
    for (int jj = 0; jj < Dx; jj++) acc += ps[jj] * Wfc[(size_t)jj*256 + tid];
    g_hfc[b*256 + tid] = acc;
}

/* ------------- 14. head: batchnorm(8) + relu + cls ------------- */
__global__ __launch_bounds__(256) void head_kernel(const float* __restrict__ gamma,
                                                   const float* __restrict__ beta,
                                                   const float* __restrict__ Wcls,
                                                   const float* __restrict__ bcls,
                                                   float* __restrict__ out) {
    __shared__ float hs[Bx*256];
    int tid = threadIdx.x;
    for (int f = tid; f < Bx*256; f += 256) hs[f] = g_hfc[f];
    __syncthreads();
    int c = tid;
    float mu = 0.f;
    #pragma unroll
    for (int b = 0; b < Bx; b++) mu += hs[b*256 + c];
    mu *= 0.125f;
    float var = 0.f;
    #pragma unroll
    for (int b = 0; b < Bx; b++) { float dd = hs[b*256 + c] - mu; var += dd*dd; }
    var *= 0.125f;
    float inv = rsqrtf(var + 1e-5f);
    float ga = gamma[c], be = beta[c];
    #pragma unroll
    for (int b = 0; b < Bx; b++) {
        float v = (hs[b*256 + c] - mu)*inv*ga + be;
        hs[b*256 + c] = fmaxf(v, 0.f);
    }
    __syncthreads();
    for (int t = tid; t < Bx*40; t += 256) {
        int b = t / 40, n = t % 40;
        float acc = bcls[n];
        for (int c2 = 0; c2 < 256; c2++) acc += hs[b*256 + c2] * Wcls[c2*40 + n];
        out[t] = acc;
    }
}

/* ------------- launch ------------- */
extern "C" void kernel_launch(void* const* d_in, const int* in_sizes, int n_in,
                              void* d_out, int out_size) {
    const float* x       = (const float*)d_in[0];
    const float* ln_w    = (const float*)d_in[1];
    const float* W_in    = (const float*)d_in[2];
    const float* conv_w  = (const float*)d_in[3];
    const float* conv_b  = (const float*)d_in[4];
    const float* W_xproj = (const float*)d_in[5];
    const float* W_dt    = (const float*)d_in[6];
    const float* dt_bias = (const float*)d_in[7];
    const float* A_log   = (const float*)d_in[8];
    const float* Dskip   = (const float*)d_in[9];
    const float* W_out   = (const float*)d_in[10];
    const float* W_fc    = (const float*)d_in[11];
    const float* b_fc    = (const float*)d_in[12];
    const float* bn_g    = (const float*)d_in[13];
    const float* bn_b    = (const float*)d_in[14];
    const float* W_cls   = (const float*)d_in[15];
    const float* b_cls   = (const float*)d_in[16];
    float* out = (float*)d_out;

    rmsnorm_kernel<<<Rx, 128>>>(x, ln_w);
    prepB_kernel<<<Dx, 256>>>(W_in);
    gemm_bf16_kernel<<<dim3(12, Rx/128), 256>>>(conv_w, conv_b);
    conv_fix_kernel<<<(256*3*DIx + 255)/256, 256>>>(conv_w, conv_b);
    xproj_kernel<<<Rx/128, 128>>>(W_xproj);
    dt_gemm_kernel<<<dim3(6, Rx/64), 256>>>(W_dt, dt_bias);
    prep_A_kernel<<<48, 256>>>(A_log);
    scan_pass1_kernel<<<dim3(6, NCH, Bx), 128>>>();
    scan_combine_kernel<<<(Bx*DIx*Sx)/256, 256>>>();
    scan_pass2_kernel<<<dim3(6, NCH, Bx), 128>>>(Dskip);
    meanx_part_kernel<<<dim3(Bx, 16), 384>>>(x);
    pooled_gemm_kernel<<<dim3(Bx, 12), 256>>>(W_out);
    fc_kernel<<<Bx, 256>>>(W_fc, b_fc);
    head_kernel<<<1, 256>>>(bn_g, bn_b, W_cls, b_cls, out);
}

// round 11
// speedup vs baseline: 2.3509x; 1.1284x over previous
#include <cuda_runtime.h>
#include <cuda_bf16.h>
#include <math.h>
#include <stdint.h>

#define Bx   8
#define Lx   4096
#define Dx   384
#define DIx  768
#define Sx   16
#define DTRx 24
#define Rx   (Bx*Lx)        /* 32768 rows */
#define NCH  32
#define CLEN (Lx/NCH)       /* 128 */
#define KEXP 1152           /* 3*Dx expanded K */

/* ------------- device scratch (static, no allocations) ------------- */
__device__ __align__(128) __nv_bfloat16 g_Abf[(size_t)Rx*KEXP];
__device__ __align__(128) __nv_bfloat16 g_Bt [(size_t)2*DIx*KEXP];
__device__ __align__(128) float g_xz [(size_t)Rx*2*DIx];
__device__ __align__(128) float g_xc [(size_t)Rx*DIx];
__device__ __align__(128) float g_dtr[(size_t)Rx*DTRx];
__device__ __align__(128) float g_Bmat[(size_t)Rx*Sx];
__device__ __align__(128) float g_Cmat[(size_t)Rx*Sx];
__device__ __align__(128) float g_dt [(size_t)Rx*DIx];
__device__ __align__(128) float g_A  [DIx*Sx];
__device__ __align__(128) float g_hfin[(size_t)Bx*NCH*DIx*Sx];
__device__ __align__(128) float g_P   [(size_t)Bx*NCH*DIx*Sx];
__device__ __align__(128) float g_w   [(size_t)Bx*NCH*DIx*Sx];
__device__ __align__(128) float g_yvl [Bx*NCH*DIx];
__device__ __align__(128) float g_yvsum[Bx*DIx];
__device__ __align__(128) float g_xpart[Bx*16*Dx];
__device__ __align__(128) float g_pooled[Bx*Dx];
__device__ __align__(128) float g_hfc[Bx*256];

__device__ __forceinline__ float softplusf(float v) {
    return v > 20.f ? v : log1pf(__expf(v));
}
__device__ __forceinline__ float siluf(float v) {
    return v / (1.f + __expf(-v));
}

/* ------------- 1. RMSNorm -> split-bf16 A' = [hi | lo | hi] ------------- */
__global__ __launch_bounds__(128) void rmsnorm_kernel(const float* __restrict__ x,
                                                      const float* __restrict__ w) {
    int row = blockIdx.x, tid = threadIdx.x;
    const float* xr = x + (size_t)row*Dx;
    float v0 = xr[tid], v1 = xr[tid+128], v2 = xr[tid+256];
    float ss = v0*v0 + v1*v1 + v2*v2;
    #pragma unroll
    for (int o = 16; o; o >>= 1) ss += __shfl_xor_sync(0xffffffffu, ss, o);
    __shared__ float sm[4];
    if ((tid & 31) == 0) sm[tid >> 5] = ss;
    __syncthreads();
    float tot = sm[0] + sm[1] + sm[2] + sm[3];
    float sc  = rsqrtf(tot * (1.f/Dx) + 1e-5f);
    __nv_bfloat16* o = g_Abf + (size_t)row*KEXP;
    float ys[3] = { v0*sc*w[tid], v1*sc*w[tid+128], v2*sc*w[tid+256] };
    int cs[3] = { tid, tid+128, tid+256 };
    #pragma unroll
    for (int q = 0; q < 3; q++) {
        __nv_bfloat16 h = __float2bfloat16(ys[q]);
        __nv_bfloat16 l = __float2bfloat16(ys[q] - __bfloat162float(h));
        o[cs[q]]       = h;
        o[384 + cs[q]] = l;
        o[768 + cs[q]] = h;
    }
}

/* ------------- 1b. build B'^T [1536][1152] = [hi | hi | lo], coalesced writes ------------- */
__global__ __launch_bounds__(128) void prepB_kernel(const float* __restrict__ W) {
    int n = blockIdx.x;  /* 0..1535 */
    __nv_bfloat16* o = g_Bt + (size_t)n*KEXP;
    for (int k = threadIdx.x; k < Dx; k += 128) {
        float v = W[(size_t)k*(2*DIx) + n];
        __nv_bfloat16 h = __float2bfloat16(v);
        __nv_bfloat16 l = __float2bfloat16(v - __bfloat162float(h));
        o[k]       = h;
        o[384 + k] = h;
        o[768 + k] = l;
    }
}

/* ------------- 2. GEMM1 bf16 TC (ldmatrix, 2-stage), fused conv epilogue ------------- */
__device__ __forceinline__ void cp16(uint32_t dst, const void* src) {
    asm volatile("cp.async.cg.shared.global [%0], [%1], 16;\n" :: "r"(dst), "l"(src));
}
__device__ __forceinline__ void cp_commit() {
    asm volatile("cp.async.commit_group;\n");
}
template<int N> __device__ __forceinline__ void cp_wait() {
    asm volatile("cp.async.wait_group %0;\n" :: "n"(N));
}
__device__ __forceinline__ void mma_bf16(float* c, const uint32_t* a, uint32_t b0, uint32_t b1) {
    asm volatile("mma.sync.aligned.m16n8k16.row.col.f32.bf16.bf16.f32 "
        "{%0,%1,%2,%3}, {%4,%5,%6,%7}, {%8,%9}, {%0,%1,%2,%3};\n"
        : "+f"(c[0]), "+f"(c[1]), "+f"(c[2]), "+f"(c[3])
        : "r"(a[0]), "r"(a[1]), "r"(a[2]), "r"(a[3]), "r"(b0), "r"(b1));
}
__device__ __forceinline__ void ldsm_x4(uint32_t* r, uint32_t addr) {
    asm volatile("ldmatrix.sync.aligned.m8n8.x4.shared.b16 {%0,%1,%2,%3}, [%4];"
        : "=r"(r[0]), "=r"(r[1]), "=r"(r[2]), "=r"(r[3]) : "r"(addr));
}

#define LDP 40            /* padded row: 32 data + 8 pad bf16 */
#define TILEB (128*LDP)   /* elements per buffer */
#define NKT 36            /* 1152/32 */
#define CROW 132          /* conv stage row stride (floats) */

__global__ __launch_bounds__(256) void gemm_bf16_kernel(const float* __restrict__ cw,
                                                        const float* __restrict__ cb) {
    const int N = 2*DIx;
    __shared__ __align__(16) __nv_bfloat16 As[2][TILEB];
    __shared__ __align__(16) __nv_bfloat16 Bs[2][TILEB];
    int tid = threadIdx.x;
    int lane = tid & 31, warp = tid >> 5;
    int warpM = warp >> 1, warpN = warp & 1;
    int bn = blockIdx.x, bm = blockIdx.y;
    int g = lane >> 2, t = lane & 3;

    int lr = tid >> 2, lc = tid & 3;
    const __nv_bfloat16* Asrc0 = g_Abf + (size_t)(bm*128 + lr)*KEXP + lc*8;
    const __nv_bfloat16* Asrc1 = Asrc0 + (size_t)64*KEXP;
    const __nv_bfloat16* Bsrc0 = g_Bt  + (size_t)(bn*128 + lr)*KEXP + lc*8;
    const __nv_bfloat16* Bsrc1 = Bsrc0 + (size_t)64*KEXP;
    uint32_t a_d0 = (uint32_t)__cvta_generic_to_shared(&As[0][lr*LDP + lc*8]);
    uint32_t a_d1 = (uint32_t)__cvta_generic_to_shared(&As[0][(64+lr)*LDP + lc*8]);
    uint32_t b_d0 = (uint32_t)__cvta_generic_to_shared(&Bs[0][lr*LDP + lc*8]);
    uint32_t b_d1 = (uint32_t)__cvta_generic_to_shared(&Bs[0][(64+lr)*LDP + lc*8]);
    const uint32_t BUFB = TILEB*2;

    uint32_t as_base = (uint32_t)__cvta_generic_to_shared(&As[0][0]);
    uint32_t bs_base = (uint32_t)__cvta_generic_to_shared(&Bs[0][0]);
    uint32_t a_lane = ((uint32_t)(lane & 15)*LDP + (lane >> 4)*8) * 2;
    uint32_t b_lane = (((uint32_t)((lane & 7) + ((lane >> 4) << 3)))*LDP
                       + (((lane >> 3) & 1) << 3)) * 2;

    float acc[2][8][4];
    #pragma unroll
    for (int i = 0; i < 2; i++)
        #pragma unroll
        for (int j = 0; j < 8; j++)
            #pragma unroll
            for (int q = 0; q < 4; q++) acc[i][j][q] = 0.f;

    cp16(a_d0, Asrc0); cp16(a_d1, Asrc1);
    cp16(b_d0, Bsrc0); cp16(b_d1, Bsrc1);
    cp_commit();

    for (int kt = 0; kt < NKT; kt++) {
        int buf = kt & 1;
        if (kt + 1 < NKT) {
            uint32_t off = (buf ^ 1) * BUFB;
            cp16(a_d0 + off, Asrc0 + (kt+1)*32);
            cp16(a_d1 + off, Asrc1 + (kt+1)*32);
            cp16(b_d0 + off, Bsrc0 + (kt+1)*32);
            cp16(b_d1 + off, Bsrc1 + (kt+1)*32);
            cp_commit();
            cp_wait<1>();
        } else {
            cp_commit();
            cp_wait<0>();
        }
        __syncthreads();
        uint32_t ab = as_base + buf*BUFB;
        uint32_t bb = bs_base + buf*BUFB;
        #pragma unroll
        for (int ks = 0; ks < 2; ks++) {
            int kk = ks*16;
            uint32_t af[2][4], bfr[4][4];
            ldsm_x4(af[0], ab + a_lane + ((warpM*32 +  0)*LDP + kk)*2);
            ldsm_x4(af[1], ab + a_lane + ((warpM*32 + 16)*LDP + kk)*2);
            #pragma unroll
            for (int jj = 0; jj < 4; jj++)
                ldsm_x4(bfr[jj], bb + b_lane + ((warpN*64 + jj*16)*LDP + kk)*2);
            #pragma unroll
            for (int jj = 0; jj < 4; jj++) {
                mma_bf16(acc[0][jj*2+0], af[0], bfr[jj][0], bfr[jj][1]);
                mma_bf16(acc[1][jj*2+0], af[1], bfr[jj][0], bfr[jj][1]);
                mma_bf16(acc[0][jj*2+1], af[0], bfr[jj][2], bfr[jj][3]);
                mma_bf16(acc[1][jj*2+1], af[1], bfr[jj][2], bfr[jj][3]);
            }
        }
        __syncthreads();
    }

    /* write xz */
    #pragma unroll
    for (int i = 0; i < 2; i++) {
        int r0 = bm*128 + warpM*32 + i*16 + g;
        #pragma unroll
        for (int j = 0; j < 8; j++) {
            int col = bn*128 + warpN*64 + j*8 + t*2;
            *(float2*)(g_xz + (size_t)r0*N + col)     = make_float2(acc[i][j][0], acc[i][j][1]);
            *(float2*)(g_xz + (size_t)(r0+8)*N + col) = make_float2(acc[i][j][2], acc[i][j][3]);
        }
    }

    /* fused causal depthwise conv + SiLU for the xp half (bn<6). */
    if (bn < 6) {
        float* cbuf = (float*)&As[0][0];
        int col = tid & 127;
        int d = bn*128 + col;
        float w0 = cw[d*4+0], w1 = cw[d*4+1], w2 = cw[d*4+2], w3 = cw[d*4+3];
        float bias = cb[d];
        int rbase = tid >> 7;
        for (int cc = 0; cc < 4; cc++) {
            __syncthreads();
            if (warpM == cc) {
                #pragma unroll
                for (int i = 0; i < 2; i++)
                    #pragma unroll
                    for (int j = 0; j < 8; j++)
                        #pragma unroll
                        for (int q = 0; q < 4; q++) {
                            int rl = i*16 + g + ((q >> 1) ? 8 : 0) + 3;
                            int c2 = warpN*64 + j*8 + t*2 + (q & 1);
                            cbuf[rl*CROW + c2] = acc[i][j][q];
                        }
            }
            if (cc > 0 && warpM == cc-1 && g >= 5) {
                #pragma unroll
                for (int j = 0; j < 8; j++)
                    #pragma unroll
                    for (int q = 2; q < 4; q++) {
                        int c2 = warpN*64 + j*8 + t*2 + (q & 1);
                        cbuf[(g-5)*CROW + c2] = acc[1][j][q];
                    }
            }
            __syncthreads();
            #pragma unroll
            for (int k = 0; k < 16; k++) {
                int row = rbase + 2*k;
                if (cc == 0 && row < 3) continue;
                float x0 = cbuf[row*CROW + col];
                float x1 = cbuf[(row+1)*CROW + col];
                float x2 = cbuf[(row+2)*CROW + col];
                float x3 = cbuf[(row+3)*CROW + col];
                float v = bias + w3*x3 + w2*x2 + w1*x1 + w0*x0;
                size_t gr = (size_t)bm*128 + cc*32 + row;
                g_xc[gr*DIx + d] = siluf(v);
            }
        }
    }
}

/* ------------- 2b. conv fixup: first 3 rows of each 128-row tile ------------- */
__global__ __launch_bounds__(256) void conv_fix_kernel(const float* __restrict__ cw,
                                                       const float* __restrict__ cb) {
    int idx = blockIdx.x*256 + threadIdx.x;
    if (idx >= 256*3*DIx) return;
    int d = idx % DIx;
    int rr = (idx / DIx) % 3;
    int tile = idx / (3*DIx);
    size_t gr = (size_t)tile*128 + rr;
    int t = (int)(gr % Lx);
    const float* xp = g_xz + gr*(2*DIx) + d;
    float acc = cb[d] + cw[d*4+3]*xp[0];
    if (t >= 1) acc += cw[d*4+2]*xp[-(long)(2*DIx)];
    if (t >= 2) acc += cw[d*4+1]*xp[-(long)2*(2*DIx)];
    if (t >= 3) acc += cw[d*4+0]*xp[-(long)3*(2*DIx)];
    g_xc[gr*DIx + d] = siluf(acc);
}

/* ------------- 4. xproj: g_xc[32768,768] @ W_xproj[768,56], 8x7 tile ------------- */
__global__ __launch_bounds__(128) void xproj_kernel(const float* __restrict__ W) {
    __shared__ float As[32][128];
    __shared__ float Ws[32][56];
    int tid = threadIdx.x;
    int m0 = blockIdx.x * 128;
    int rm = (tid >> 3) * 8, cn = (tid & 7) * 7;
    float acc[8][7] = {};
    for (int k0 = 0; k0 < DIx; k0 += 32) {
        #pragma unroll
        for (int l = 0; l < 8; l++) {
            int f = tid + l*128;
            int r = f >> 3, c4 = (f & 7)*4;
            float4 v = *(const float4*)(g_xc + (size_t)(m0+r)*DIx + k0 + c4);
            As[c4+0][r] = v.x; As[c4+1][r] = v.y; As[c4+2][r] = v.z; As[c4+3][r] = v.w;
        }
        #pragma unroll
        for (int l = 0; l < 4; l++) {
            int f = tid + l*128;
            if (f < 448) {
                int kr = f / 14, c4 = (f % 14)*4;
                *(float4*)(&Ws[kr][c4]) = *(const float4*)(W + (size_t)(k0+kr)*56 + c4);
            }
        }
        __syncthreads();
        #pragma unroll
        for (int k = 0; k < 32; k++) {
            float ra[8], rw[7];
            #pragma unroll
            for (int i = 0; i < 8; i++) ra[i] = As[k][rm+i];
            #pragma unroll
            for (int j = 0; j < 7; j++) rw[j] = Ws[k][cn+j];
            #pragma unroll
            for (int i = 0; i < 8; i++)
                #pragma unroll
                for (int j = 0; j < 7; j++) acc[i][j] += ra[i]*rw[j];
        }
        __syncthreads();
    }
    #pragma unroll
    for (int i = 0; i < 8; i++)
        #pragma unroll
        for (int j = 0; j < 7; j++) {
            int cc = cn + j;
            size_t row = (size_t)(m0 + rm + i);
            float v = acc[i][j];
            if (cc < 24)       g_dtr[row*DTRx + cc] = v;
            else if (cc < 40)  g_Bmat[row*Sx + (cc-24)] = v;
            else               g_Cmat[row*Sx + (cc-40)] = v;
        }
}

/* ------------- 5. dt GEMM: g_dtr[32768,24] @ W_dt[24,768] + bias -> softplus ------------- */
__global__ __launch_bounds__(256) void dt_gemm_kernel(const float* __restrict__ Wdt,
                                                      const float* __restrict__ bias) {
    __shared__ float As[64][24];
    __shared__ float Ws[24][128];
    int tid = threadIdx.x;
    int n0 = blockIdx.x * 128, m0 = blockIdx.y * 64;
    #pragma unroll
    for (int l = 0; l < 2; l++) {
        int f = tid + l*256;
        if (f < 384) {
            int r = f / 6, c4 = (f % 6)*4;
            *(float4*)(&As[r][c4]) = *(const float4*)(g_dtr + (size_t)(m0+r)*DTRx + c4);
        }
    }
    #pragma unroll
    for (int l = 0; l < 3; l++) {
        int f = tid + l*256;
        int kr = f >> 5, c4 = (f & 31)*4;
        *(float4*)(&Ws[kr][c4]) = *(const float4*)(Wdt + (size_t)kr*DIx + n0 + c4);
    }
    __syncthreads();
    int rm = (tid >> 5)*8, cn = (tid & 31)*4;
    float acc[8][4] = {};
    #pragma unroll
    for (int k = 0; k < 24; k++) {
        float rw0 = Ws[k][cn], rw1 = Ws[k][cn+1], rw2 = Ws[k][cn+2], rw3 = Ws[k][cn+3];
        #pragma unroll
        for (int i = 0; i < 8; i++) {
            float a = As[rm+i][k];
            acc[i][0] += a*rw0; acc[i][1] += a*rw1; acc[i][2] += a*rw2; acc[i][3] += a*rw3;
        }
    }
    float b0 = bias[n0+cn], b1 = bias[n0+cn+1], b2 = bias[n0+cn+2], b3 = bias[n0+cn+3];
    #pragma unroll
    for (int i = 0; i < 8; i++) {
        float4 o;
        o.x = softplusf(acc[i][0] + b0);
        o.y = softplusf(acc[i][1] + b1);
        o.z = softplusf(acc[i][2] + b2);
        o.w = softplusf(acc[i][3] + b3);
        *(float4*)(g_dt + (size_t)(m0+rm+i)*DIx + n0 + cn) = o;
    }
}

/* ------------- 6. A = -exp(A_log) ------------- */
__global__ void prep_A_kernel(const float* __restrict__ A_log) {
    int i = blockIdx.x*256 + threadIdx.x;
    if (i < DIx*Sx) g_A[i] = -__expf(A_log[i]);
}

/* ------------- 7. SINGLE scan pass: local scan from h=0, emits
   h_local_fin[16], P=prod(exp(dt*a))[16], w[16]=sum_t sv*C*P, yv_local ------------- */
__global__ __launch_bounds__(128) void scan_single_kernel(const float* __restrict__ Dskip) {
    int d = blockIdx.x*128 + threadIdx.x;
    int c = blockIdx.y, b = blockIdx.z;
    float a[Sx], h[Sx], P[Sx], w[Sx];
    const float4* Ap = (const float4*)(g_A + d*Sx);
    #pragma unroll
    for (int q = 0; q < 4; q++) {
        float4 v = Ap[q];
        a[q*4+0] = v.x; a[q*4+1] = v.y; a[q*4+2] = v.z; a[q*4+3] = v.w;
    }
    #pragma unroll
    for (int s = 0; s < Sx; s++) { h[s] = 0.f; P[s] = 1.f; w[s] = 0.f; }
    int row0 = b*Lx + c*CLEN;
    const float* dtp = g_dt + (size_t)row0*DIx + d;
    const float* xp  = g_xc + (size_t)row0*DIx + d;
    const float* zp  = g_xz + (size_t)row0*(2*DIx) + DIx + d;
    const float4* Bp = (const float4*)(g_Bmat + (size_t)row0*Sx);
    const float4* Cp = (const float4*)(g_Cmat + (size_t)row0*Sx);
    float Dk = Dskip[d];
    float yvl = 0.f;
    #pragma unroll 2
    for (int t = 0; t < CLEN; t++) {
        float dv = dtp[(size_t)t*DIx];
        float xv = xp[(size_t)t*DIx];
        float zv = zp[(size_t)t*(2*DIx)];
        float4 q0 = Bp[t*4+0], q1 = Bp[t*4+1], q2 = Bp[t*4+2], q3 = Bp[t*4+3];
        float Bv[16] = {q0.x,q0.y,q0.z,q0.w,q1.x,q1.y,q1.z,q1.w,
                        q2.x,q2.y,q2.z,q2.w,q3.x,q3.y,q3.z,q3.w};
        float4 r0 = Cp[t*4+0], r1 = Cp[t*4+1], r2 = Cp[t*4+2], r3 = Cp[t*4+3];
        float Cv[16] = {r0.x,r0.y,r0.z,r0.w,r1.x,r1.y,r1.z,r1.w,
                        r2.x,r2.y,r2.z,r2.w,r3.x,r3.y,r3.z,r3.w};
        float c1 = dv*xv;
        float sv = siluf(zv);
        float y = 0.f;
        #pragma unroll
        for (int s = 0; s < Sx; s++) {
            float e = __expf(dv*a[s]);
            P[s] *= e;
            h[s] = e*h[s] + c1*Bv[s];
            y += h[s]*Cv[s];
            w[s] += sv*Cv[s]*P[s];
        }
        yvl += (y + xv*Dk) * sv;
    }
    size_t base = (((size_t)b*NCH + c)*DIx + d)*Sx;
    #pragma unroll
    for (int s = 0; s < Sx; s += 4) {
        *(float4*)(g_hfin + base + s) = make_float4(h[s], h[s+1], h[s+2], h[s+3]);
        *(float4*)(g_P    + base + s) = make_float4(P[s], P[s+1], P[s+2], P[s+3]);
        *(float4*)(g_w    + base + s) = make_float4(w[s], w[s+1], w[s+2], w[s+3]);
    }
    g_yvl[(b*NCH + c)*DIx + d] = yvl;
}

/* ------------- 8. sequential chunk combine: h0 chain + yv correction ------------- */
__global__ __launch_bounds__(256) void scan_combine_kernel() {
    int gid = blockIdx.x*256 + threadIdx.x;  /* < 8*768*16 = 98304 */
    int s = gid & 15;
    int d = (gid >> 4) % DIx;
    int b = gid / (DIx*Sx);
    float h0 = 0.f, yv = 0.f;
    for (int c = 0; c < NCH; c++) {
        size_t base = (((size_t)b*NCH + c)*DIx + d)*Sx + s;
        float Pv = g_P[base];
        float hf = g_hfin[base];
        float wv = g_w[base];
        float corr = h0 * wv;
        corr += __shfl_xor_sync(0xffffffffu, corr, 1);
        corr += __shfl_xor_sync(0xffffffffu, corr, 2);
        corr += __shfl_xor_sync(0xffffffffu, corr, 4);
        corr += __shfl_xor_sync(0xffffffffu, corr, 8);
        if (s == 0) yv += corr + g_yvl[(b*NCH + c)*DIx + d];
        h0 = Pv*h0 + hf;
    }
    if (s == 0) g_yvsum[b*DIx + d] = yv;
}

/* ------------- 10. mean over L of x (partials, deterministic) ------------- */
__global__ __launch_bounds__(384) void meanx_part_kernel(const float* __restrict__ x) {
    int b = blockIdx.x, cz = blockIdx.y, j = threadIdx.x;
    float acc = 0.f;
    for (int i = 0; i < 256; i++)
        acc += x[((size_t)b*Lx + cz*256 + i)*Dx + j];
    g_xpart[(b*16 + cz)*Dx + j] = acc;
}

/* ------------- 12. pooled = (sum_x + yvsum @ W_out)/L ------------- */
__global__ __launch_bounds__(256) void pooled_gemm_kernel(const float* __restrict__ Wout) {
    __shared__ float myv[DIx];
    __shared__ float red[8][32];
    int tid = threadIdx.x;
    int b = blockIdx.x, j0 = blockIdx.y*32;
    for (int f = tid; f < DIx; f += 256) myv[f] = g_yvsum[b*DIx + f];
    __syncthreads();
    int j = j0 + (tid & 31), seg = tid >> 5;
    float acc = 0.f;
    for (int d = seg*96; d < seg*96 + 96; d++)
        acc += myv[d] * Wout[(size_t)d*Dx + j];
    red[seg][tid & 31] = acc;
    __syncthreads();
    if (seg == 0) {
        float tot = 0.f;
        #pragma unroll
        for (int s = 0; s < 8; s++) tot += red[s][tid];
        float mx = 0.f;
        #pragma unroll
        for (int cz = 0; cz < 16; cz++) mx += g_xpart[(b*16 + cz)*Dx + j];
        g_pooled[b*Dx + j] = (mx + tot) * (1.f/Lx);
    }
}

/* ------------- 13. fc: pooled[8,384] @ W_fc[384,256] + b_fc ------------- */
__global__ __launch_bounds__(256) void fc_kernel(const float* __restrict__ Wfc,
                                                 const float* __restrict__ bfc) {
    __shared__ float ps[Dx];
    int b = blockIdx.x, tid = threadIdx.x;
    for (int f = tid; f < Dx; f += 256) ps[f] = g_pooled[b*Dx + f];
    __syncthreads();
    float acc = bfc[tid];
    for (int jj = 0; jj < Dx; jj++) acc += ps[jj] * Wfc[(size_t)jj*256 + tid];
    g_hfc[b*256 + tid] = acc;
}

/* ------------- 14. head: batchnorm(8) + relu + cls ------------- */
__global__ __launch_bounds__(256) void head_kernel(const float* __restrict__ gamma,
                                                   const float* __restrict__ beta,
                                                   const float* __restrict__ Wcls,
                                                   const float* __restrict__ bcls,
                                                   float* __restrict__ out) {
    __shared__ float hs[Bx*256];
    int tid = threadIdx.x;
    for (int f = tid; f < Bx*256; f += 256) hs[f] = g_hfc[f];
    __syncthreads();
    int c = tid;
    float mu = 0.f;
    #pragma unroll
    for (int b = 0; b < Bx; b++) mu += hs[b*256 + c];
    mu *= 0.125f;
    float var = 0.f;
    #pragma unroll
    for (int b = 0; b < Bx; b++) { float dd = hs[b*256 + c] - mu; var += dd*dd; }
    var *= 0.125f;
    float inv = rsqrtf(var + 1e-5f);
    float ga = gamma[c], be = beta[c];
    #pragma unroll
    for (int b = 0; b < Bx; b++) {
        float v = (hs[b*256 + c] - mu)*inv*ga + be;
        hs[b*256 + c] = fmaxf(v, 0.f);
    }
    __syncthreads();
    for (int t = tid; t < Bx*40; t += 256) {
        int b = t / 40, n = t % 40;
        float acc = bcls[n];
        for (int c2 = 0; c2 < 256; c2++) acc += hs[b*256 + c2] * Wcls[c2*40 + n];
        out[t] = acc;
    }
}

/* ------------- launch ------------- */
extern "C" void kernel_launch(void* const* d_in, const int* in_sizes, int n_in,
                              void* d_out, int out_size) {
    const float* x       = (const float*)d_in[0];
    const float* ln_w    = (const float*)d_in[1];
    const float* W_in    = (const float*)d_in[2];
    const float* conv_w  = (const float*)d_in[3];
    const float* conv_b  = (const float*)d_in[4];
    const float* W_xproj = (const float*)d_in[5];
    const float* W_dt    = (const float*)d_in[6];
    const float* dt_bias = (const float*)d_in[7];
    const float* A_log   = (const float*)d_in[8];
    const float* Dskip   = (const float*)d_in[9];
    const float* W_out   = (const float*)d_in[10];
    const float* W_fc    = (const float*)d_in[11];
    const float* b_fc    = (const float*)d_in[12];
    const float* bn_g    = (const float*)d_in[13];
    const float* bn_b    = (const float*)d_in[14];
    const float* W_cls   = (const float*)d_in[15];
    const float* b_cls   = (const float*)d_in[16];
    float* out = (float*)d_out;

    rmsnorm_kernel<<<Rx, 128>>>(x, ln_w);
    prepB_kernel<<<2*DIx, 128>>>(W_in);
    gemm_bf16_kernel<<<dim3(12, Rx/128), 256>>>(conv_w, conv_b);
    conv_fix_kernel<<<(256*3*DIx + 255)/256, 256>>>(conv_w, conv_b);
    xproj_kernel<<<Rx/128, 128>>>(W_xproj);
    dt_gemm_kernel<<<dim3(6, Rx/64), 256>>>(W_dt, dt_bias);
    prep_A_kernel<<<48, 256>>>(A_log);
    scan_single_kernel<<<dim3(6, NCH, Bx), 128>>>(Dskip);
    scan_combine_kernel<<<(Bx*DIx*Sx)/256, 256>>>();
    meanx_part_kernel<<<dim3(Bx, 16), 384>>>(x);
    pooled_gemm_kernel<<<dim3(Bx, 12), 256>>>(W_out);
    fc_kernel<<<Bx, 256>>>(W_fc, b_fc);
    head_kernel<<<1, 256>>>(bn_g, bn_b, W_cls, b_cls, out);
}